// round 8
// baseline (speedup 1.0000x reference)
#include <cuda_runtime.h>
#include <cuda_bf16.h>
#include <cstdint>

// ---------------- problem constants ----------------
#define B_BATCH 64
#define N_NODES 1024
#define S_LOC   12
#define HID     64
#define PAT     32
#define M_GLB   64
#define S_GLB   6
#define M_LOC   64
#define D_EMB   16
#define KDIM    768           // S_LOC * HID
#define CDIM    128           // M_LOC + M_GLB
#define ROWS    65536         // B_BATCH * N_NODES
#define NCHUNK  12            // K chunks of 64

// tcgen05 is arch-SPECIFIC: only emit its PTX in the sm_103a/sm_100a pass.
#if defined(__CUDA_ARCH_FEAT_SM103_ALL) || defined(__CUDA_ARCH_FEAT_SM100_ALL) || \
    (defined(__CUDA_ARCH_SPECIFIC__) && (__CUDA_ARCH_SPECIFIC__ == 1030 || __CUDA_ARCH_SPECIFIC__ == 1000))
#define HAS_TCGEN05 1
#else
#define HAS_TCGEN05 0
#endif

// ---------------- static device scratch ----------------
__device__ __align__(16) float g_A[KDIM * CDIM];           // folded weights  [768][128]
__device__ __align__(16) float g_bias[CDIM];
__device__ __align__(16) float g_Lm[M_LOC * PAT];
__device__ __align__(16) float g_Gm[M_GLB * PAT];
__device__ __align__(16) float g_fused[N_NODES * B_BATCH * 64];  // [n][b][64] = 16.8 MB
// pre-swizzled bf16 B operand (hi/lo), [chunk][128 n-rows][128 bytes]
__device__ __align__(16) unsigned char g_Bhi[NCHUNK * 128 * 128];
__device__ __align__(16) unsigned char g_Blo[NCHUNK * 128 * 128];

// ---------------- helpers legal on all targets ----------------
__device__ __forceinline__ uint32_t su32(const void* p) {
    uint32_t a;
    asm("{ .reg .u64 t; cvta.to.shared.u64 t, %1; cvt.u32.u64 %0, t; }" : "=r"(a) : "l"(p));
    return a;
}
__device__ __forceinline__ uint32_t bf16pack(float x0, float x1) {
    uint32_t r;
    asm("cvt.rn.bf16x2.f32 %0, %1, %2;" : "=r"(r) : "f"(x1), "f"(x0));
    return r;
}
__device__ __forceinline__ void bf16split(float x0, float x1, uint32_t& hi, uint32_t& lo) {
    hi = bf16pack(x0, x1);
    float h0 = __uint_as_float(hi << 16);
    float h1 = __uint_as_float(hi & 0xffff0000u);
    lo = bf16pack(x0 - h0, x1 - h1);
}
__device__ __forceinline__ void cp16(uint32_t saddr, const void* gaddr) {
    asm volatile("cp.async.cg.shared.global [%0], [%1], 16;" :: "r"(saddr), "l"(gaddr) : "memory");
}

#if HAS_TCGEN05
__device__ __forceinline__ uint32_t elect1() {
    uint32_t r;
    asm volatile("{ .reg .pred p; elect.sync _|p, 0xFFFFFFFF; selp.b32 %0, 1, 0, p; }" : "=r"(r));
    return r;
}
__device__ __forceinline__ uint64_t mkdesc(uint32_t saddr) {
    // SW128 K-major: layout=2, version=1, SBO=64, LBO=1
    return 0x4000404000010000ULL | ((uint64_t)(saddr >> 4) & 0x3FFF);
}
__device__ __forceinline__ void mma_f16_ss(uint32_t d, uint64_t ad, uint64_t bd,
                                           uint32_t idesc, uint32_t en) {
    asm volatile(
        "{\n\t.reg .pred p;\n\tsetp.ne.u32 p, %4, 0;\n\t"
        "tcgen05.mma.cta_group::1.kind::f16 [%0], %1, %2, %3, {%5, %5, %5, %5}, p;\n\t}"
        :: "r"(d), "l"(ad), "l"(bd), "r"(idesc), "r"(en), "r"(0u) : "memory");
}
#define MBAR_INIT(a, n) asm volatile("mbarrier.init.shared.b64 [%0], %1;" :: "r"(a), "r"(n) : "memory")
#define MBAR_WAITP(addr, par) do {                                                      \
    uint32_t _m = (addr), _p = (par), _d;                                               \
    asm volatile("{\n\t.reg .pred p;\n\t"                                               \
        "mbarrier.try_wait.parity.acquire.cta.shared::cta.b64 p, [%1], %2;\n\t"         \
        "selp.b32 %0, 1, 0, p;\n\t}" : "=r"(_d) : "r"(_m), "r"(_p) : "memory");         \
    if (!_d) {                                                                          \
        asm volatile("{\n\t.reg .pred P1;\n\tWL_%=:\n\t"                                \
            "mbarrier.try_wait.parity.acquire.cta.shared::cta.b64 P1, [%0], %1, 0x989680;\n\t" \
            "@P1 bra.uni WD_%=;\n\tbra.uni WL_%=;\n\tWD_%=:\n\t}"                       \
            :: "r"(_m), "r"(_p) : "memory");                                            \
    }                                                                                   \
} while (0)
#define TC_COMMIT(a) asm volatile("tcgen05.commit.cta_group::1.mbarrier::arrive::one.shared::cluster.b64 [%0];" :: "r"(a) : "memory")
#define TC_WAITLD()  asm volatile("tcgen05.wait::ld.sync.aligned;" ::: "memory")
#define LDTM32(r, a) asm volatile(                                                      \
    "tcgen05.ld.sync.aligned.32x32b.x32.b32 "                                           \
    "{%0, %1, %2, %3, %4, %5, %6, %7, %8, %9, %10, %11, %12, %13, %14, %15, "           \
    " %16, %17, %18, %19, %20, %21, %22, %23, %24, %25, %26, %27, %28, %29, %30, %31}, [%32];" \
    : "=r"((r)[0]), "=r"((r)[1]), "=r"((r)[2]), "=r"((r)[3]),                           \
      "=r"((r)[4]), "=r"((r)[5]), "=r"((r)[6]), "=r"((r)[7]),                           \
      "=r"((r)[8]), "=r"((r)[9]), "=r"((r)[10]), "=r"((r)[11]),                         \
      "=r"((r)[12]), "=r"((r)[13]), "=r"((r)[14]), "=r"((r)[15]),                       \
      "=r"((r)[16]), "=r"((r)[17]), "=r"((r)[18]), "=r"((r)[19]),                       \
      "=r"((r)[20]), "=r"((r)[21]), "=r"((r)[22]), "=r"((r)[23]),                       \
      "=r"((r)[24]), "=r"((r)[25]), "=r"((r)[26]), "=r"((r)[27]),                       \
      "=r"((r)[28]), "=r"((r)[29]), "=r"((r)[30]), "=r"((r)[31])                        \
    : "r"(a))
// idesc: fp32 accum, bf16 x bf16, M=128, N=128, K-major both
#define IDESC_BF16 0x8200490u
#endif  // HAS_TCGEN05

// ================= P1: A[k][c] = folded bank weights (coalesced) =================
__global__ __launch_bounds__(256) void pA_kernel(const float* __restrict__ G,
                                                 const float* __restrict__ L,
                                                 const float* __restrict__ Wq) {
    __shared__ float sBank[S_LOC * PAT];
    __shared__ float sWq[HID][PAT + 1];
    int c = blockIdx.x, tid = threadIdx.x;
    #pragma unroll
    for (int i = tid; i < HID * PAT; i += 256) sWq[i >> 5][i & 31] = Wq[i];
    if (c < 64) {
        if (tid < S_LOC * PAT) sBank[tid] = L[c * (S_LOC * PAT) + tid];
        if (tid + 256 < S_LOC * PAT) sBank[tid + 256] = L[c * (S_LOC * PAT) + tid + 256];
    } else {
        if (tid < S_GLB * PAT) sBank[tid] = G[(c - 64) * (S_GLB * PAT) + tid];
    }
    __syncthreads();
    float scale = (c < 64) ? 1.0f : 0.5f;
    #pragma unroll
    for (int j = 0; j < 3; j++) {
        int k = j * 256 + tid;
        int s = k >> 6, h = k & 63;
        int base = (c < 64) ? s * PAT : (s >> 1) * PAT;
        float v = 0.f;
        #pragma unroll
        for (int p = 0; p < PAT; p++) v += sWq[h][p] * sBank[base + p];
        g_A[k * CDIM + c] = v * scale;
    }
}

// ================= P2: bias + bank means fused =================
__global__ void pAux_kernel(const float* __restrict__ G, const float* __restrict__ L,
                            const float* __restrict__ bq) {
    if (blockIdx.x == 0) {
        int c = threadIdx.x;
        if (c >= 128) return;
        float v = 0.f;
        if (c < 64) {
            for (int s = 0; s < S_LOC; s++)
                #pragma unroll
                for (int p = 0; p < PAT; p++) v += bq[p] * L[c * (S_LOC * PAT) + s * PAT + p];
        } else {
            for (int s = 0; s < S_GLB; s++)
                #pragma unroll
                for (int p = 0; p < PAT; p++) v += bq[p] * G[(c - 64) * (S_GLB * PAT) + s * PAT + p];
        }
        g_bias[c] = v;
    } else {
        int idx = (blockIdx.x - 1) * 256 + threadIdx.x;
        if (idx >= 2048) return;
        int m = idx >> 5, p = idx & 31;
        float lm = 0.f, gm = 0.f;
        for (int s = 0; s < S_LOC; s++) lm += L[m * (S_LOC * PAT) + s * PAT + p];
        for (int s = 0; s < S_GLB; s++) gm += G[m * (S_GLB * PAT) + s * PAT + p];
        g_Lm[idx] = lm * (1.f / 12.f);
        g_Gm[idx] = gm * (1.f / 6.f);
    }
}

// ================= P3: pre-swizzled bf16 hi/lo split of B = g_A^T =================
__global__ void pBsw_kernel() {
    int t = blockIdx.x * 256 + threadIdx.x;          // < 12288
    int ci = t >> 10;
    int kq = (t >> 7) & 7;
    int n  = t & 127;                                // lane-fastest: coalesced g_A reads
    uint32_t hi[4], lo[4];
    #pragma unroll
    for (int p = 0; p < 4; p++) {
        int k0 = ci * 64 + kq * 8 + 2 * p;
        float x0 = g_A[(k0 + 0) * CDIM + n];
        float x1 = g_A[(k0 + 1) * CDIM + n];
        bf16split(x0, x1, hi[p], lo[p]);
    }
    int off = n * 128 + kq * 16;
    int swo = off ^ ((off >> 3) & 0x70);
    *(uint4*)(g_Bhi + ci * 16384 + swo) = make_uint4(hi[0], hi[1], hi[2], hi[3]);
    *(uint4*)(g_Blo + ci * 16384 + swo) = make_uint4(lo[0], lo[1], lo[2], lo[3]);
}

// ================= K1: tcgen05 bf16x3 GEMM + fused softmax/context =================
// smem layout (no overlaps):
//   [0..4)        tmem ptr
//   [16..32)      2 mbarriers
//   [64..576)     bias (128 f)
//   [1024..9216)  sLm [64][32]
//   [9216..17408) sGm [64][32]
//   [17408..148480)  2 x 64KB stages
//   [148480..216064) slog [128][132] (logits -> attn, dedicated region)
#define SMEM_STAGE0 17408
#define SMEM_ATTN   (SMEM_STAGE0 + 2 * 65536)
#define K1_SMEM     (SMEM_ATTN + 128 * 132 * 4)
__global__ __launch_bounds__(256, 1) void k1_tc(const float* __restrict__ H) {
#if HAS_TCGEN05
    extern __shared__ __align__(1024) char smem[];
    const int tid = threadIdx.x, w = tid >> 5, lane = tid & 31;
    const int row0 = blockIdx.x << 7;
    const int b_idx = row0 >> 10;            // batch (fixed per block; 128 | 1024)
    const int n0 = row0 & 1023;              // first node of this block
    uint32_t sb = su32(smem);

    if (w == 0) {
        asm volatile("tcgen05.alloc.cta_group::1.sync.aligned.shared::cta.b32 [%0], %1;"
                     :: "r"(sb), "r"(128u) : "memory");
    } else {
        asm volatile("tcgen05.relinquish_alloc_permit.cta_group::1.sync.aligned;");
    }
    if (tid == 0) { MBAR_INIT(sb + 16, 1); MBAR_INIT(sb + 24, 1); }
    float* sbias = (float*)(smem + 64);
    float* sLmS  = (float*)(smem + 1024);
    float* sGmS  = (float*)(smem + 9216);
    if (tid < 128) sbias[tid] = g_bias[tid];
    #pragma unroll
    for (int i = 0; i < 8; i++) {
        sLmS[i * 256 + tid] = g_Lm[i * 256 + tid];
        sGmS[i * 256 + tid] = g_Gm[i * 256 + tid];
    }
    __syncthreads();
    uint32_t tmem;
    asm("ld.shared.b32 %0, [%1];" : "=r"(tmem) : "r"(sb));

    for (int c = 0; c < NCHUNK; c++) {
        const int st = c & 1;
        char* buf = smem + SMEM_STAGE0 + st * 65536;
        const uint32_t bufb = sb + SMEM_STAGE0 + st * 65536;
        const int u = c >> 1;
        if (u >= 1) MBAR_WAITP(sb + 16 + st * 8, (uint32_t)((u - 1) & 1));

        // stage B via cp.async (pre-swizzled)
        {
            const char* bh = (const char*)g_Bhi + c * 16384 + tid * 16;
            const char* bl = (const char*)g_Blo + c * 16384 + tid * 16;
            uint32_t dh = bufb + 32768 + tid * 16;
            uint32_t dl = bufb + 49152 + tid * 16;
            #pragma unroll
            for (int i = 0; i < 4; i++) {
                cp16(dh + i * 4096, bh + i * 4096);
                cp16(dl + i * 4096, bl + i * 4096);
            }
            asm volatile("cp.async.commit_group;" ::: "memory");
        }
        // stage A: load H fp32, split hi/lo, swizzled STS
        #pragma unroll
        for (int it = 0; it < 4; it++) {
            int task = it * 256 + tid;
            int r = task >> 3, kq = task & 7;
            const float* hp = H + (size_t)(row0 + r) * KDIM + c * 64 + kq * 8;
            float4 u0 = *(const float4*)hp;
            float4 u1 = *(const float4*)(hp + 4);
            uint32_t hi[4], lo[4];
            bf16split(u0.x, u0.y, hi[0], lo[0]);
            bf16split(u0.z, u0.w, hi[1], lo[1]);
            bf16split(u1.x, u1.y, hi[2], lo[2]);
            bf16split(u1.z, u1.w, hi[3], lo[3]);
            int off = r * 128 + kq * 16;
            int swo = off ^ ((off >> 3) & 0x70);
            *(uint4*)(buf + swo)         = make_uint4(hi[0], hi[1], hi[2], hi[3]);
            *(uint4*)(buf + 16384 + swo) = make_uint4(lo[0], lo[1], lo[2], lo[3]);
        }
        asm volatile("cp.async.wait_group 0;" ::: "memory");
        asm volatile("fence.proxy.async.shared::cta;" ::: "memory");
        __syncthreads();

        if (w == 0 && elect1()) {
            uint64_t ah = mkdesc(bufb);
            uint64_t al = mkdesc(bufb + 16384);
            uint64_t bh = mkdesc(bufb + 32768);
            uint64_t bl = mkdesc(bufb + 49152);
            #pragma unroll
            for (int ks = 0; ks < 4; ks++) {
                uint32_t en0 = (c == 0 && ks == 0) ? 0u : 1u;
                mma_f16_ss(tmem, ah + 2 * ks, bh + 2 * ks, IDESC_BF16, en0);
                mma_f16_ss(tmem, ah + 2 * ks, bl + 2 * ks, IDESC_BF16, 1u);
                mma_f16_ss(tmem, al + 2 * ks, bh + 2 * ks, IDESC_BF16, 1u);
            }
            TC_COMMIT(sb + 16 + st * 8);
        }
    }

    // stage-1 barrier: in-loop waits consumed completions 1..5; wait #6 (parity 1).
    MBAR_WAITP(sb + 24, 1u);
    asm volatile("tcgen05.fence::after_thread_sync;" ::: "memory");

    // ---- epilogue part 1 (R6-proven LDTM pattern, STS instead of STG) ----
    float* slog = (float*)(smem + SMEM_ATTN);      // [128][132] padded rows
    if (w < 4) {
        #pragma unroll
        for (int base = 0; base < 128; base += 32) {
            uint32_t dr[32];
            LDTM32(dr, tmem + base);
            TC_WAITLD();
            float* lp = slog + (w * 32 + lane) * 132 + base;
            #pragma unroll
            for (int j = 0; j < 32; j++) lp[j] = __uint_as_float(dr[j]) + sbias[base + j];
        }
        asm volatile("tcgen05.fence::before_thread_sync;" ::: "memory");
    }
    __syncthreads();
    if (w == 0) {
        asm volatile("tcgen05.dealloc.cta_group::1.sync.aligned.b32 %0, %1;"
                     :: "r"(tmem), "r"(128u));
    }

    // ---- epilogue part 2 (k2-proven softmax/ctx math, smem-sourced) ----
    for (int i = 0; i < 16; i++) {
        int r = w * 16 + i;
        float* lp = slog + r * 132;
        float v0 = lp[lane], v1 = lp[lane + 32];
        float v2 = lp[lane + 64], v3 = lp[lane + 96];

        float mx = fmaxf(v0, v1);
        #pragma unroll
        for (int o = 16; o; o >>= 1) mx = fmaxf(mx, __shfl_xor_sync(0xffffffffu, mx, o));
        float e0 = __expf(v0 - mx), e1 = __expf(v1 - mx);
        float s = e0 + e1;
        #pragma unroll
        for (int o = 16; o; o >>= 1) s += __shfl_xor_sync(0xffffffffu, s, o);
        float inv = 1.f / s;

        float mx2 = fmaxf(v2, v3);
        #pragma unroll
        for (int o = 16; o; o >>= 1) mx2 = fmaxf(mx2, __shfl_xor_sync(0xffffffffu, mx2, o));
        float e2 = __expf(v2 - mx2), e3 = __expf(v3 - mx2);
        float s2 = e2 + e3;
        #pragma unroll
        for (int o = 16; o; o >>= 1) s2 += __shfl_xor_sync(0xffffffffu, s2, o);
        float inv2 = 1.f / s2;

        lp[lane] = e0 * inv;  lp[lane + 32] = e1 * inv;
        lp[lane + 64] = e2 * inv2; lp[lane + 96] = e3 * inv2;
        __syncwarp();

        float lc = 0.f, gc = 0.f;
        #pragma unroll 8
        for (int m = 0; m < 64; m++) {
            lc += lp[m]      * sLmS[m * 32 + lane];
            gc += lp[64 + m] * sGmS[m * 32 + lane];
        }
        float* op = g_fused + (size_t)(n0 + r) * (B_BATCH * 64) + b_idx * 64;
        op[lane] = lc;
        op[lane + 32] = gc;
        __syncwarp();
    }
#else
    // Generic-arch fallback (never executed on sm_103a; keeps compute_103 PTX legal).
    const int tid = threadIdx.x;
    const int row0 = blockIdx.x << 7;
    const int b_idx = row0 >> 10, n0 = row0 & 1023;
    if (tid < 128) {
        size_t row = row0 + tid;
        float sim[128];
        #pragma unroll
        for (int c = 0; c < 128; c++) sim[c] = g_bias[c];
        for (int k = 0; k < KDIM; k++) {
            float h = H[row * KDIM + k];
            #pragma unroll
            for (int c = 0; c < 128; c++) sim[c] += h * g_A[k * CDIM + c];
        }
        float mx1 = -3.4e38f, mx2 = -3.4e38f;
        for (int c = 0; c < 64; c++)  mx1 = fmaxf(mx1, sim[c]);
        for (int c = 64; c < 128; c++) mx2 = fmaxf(mx2, sim[c]);
        float s1 = 0, s2 = 0;
        for (int c = 0; c < 64; c++)  { sim[c] = __expf(sim[c] - mx1); s1 += sim[c]; }
        for (int c = 64; c < 128; c++){ sim[c] = __expf(sim[c] - mx2); s2 += sim[c]; }
        float* op = g_fused + (size_t)(n0 + tid) * (B_BATCH * 64) + b_idx * 64;
        for (int p = 0; p < 32; p++) {
            float lc = 0, gc = 0;
            for (int m = 0; m < 64; m++) {
                lc += sim[m] * g_Lm[m * 32 + p];
                gc += sim[64 + m] * g_Gm[m * 32 + p];
            }
            op[p] = lc / s1;
            op[p + 32] = gc / s2;
        }
    }
#endif
}

// ================= K3: out[b][n][h] = fused[n][b][:] @ (emb[n] @ pool) =================
__global__ __launch_bounds__(256) void k3_out(const float* __restrict__ emb,
                                              const float* __restrict__ pool,
                                              float* __restrict__ out) {
    __shared__ float se[D_EMB];
    __shared__ float snw[64 * 64];    // [f][h]
    __shared__ float sfu[64 * 64];    // [b][f]
    int n = blockIdx.x, tid = threadIdx.x;
    if (tid < D_EMB) se[tid] = emb[n * D_EMB + tid];
    {
        const float4* fs = (const float4*)(g_fused + (size_t)n * 4096);
        float4* fd = (float4*)sfu;
        #pragma unroll
        for (int i = 0; i < 4; i++) fd[tid + i * 256] = fs[tid + i * 256];
    }
    __syncthreads();
    #pragma unroll
    for (int j = 0; j < 16; j++) {
        int idx = j * 256 + tid;                      // f*64 + h
        float v = 0.f;
        #pragma unroll
        for (int d = 0; d < D_EMB; d++) v += se[d] * pool[d * 4096 + idx];
        snw[idx] = v;
    }
    __syncthreads();
    int h2 = (tid & 31);                              // h pair: h = 2*h2
    int bg = tid >> 5;                                // 8 b-groups
    const float2* snw2 = (const float2*)snw;
    #pragma unroll
    for (int bb = 0; bb < 8; bb++) {
        int b = bg * 8 + bb;
        const float* fu = sfu + b * 64;
        float2 acc = make_float2(0.f, 0.f);
        #pragma unroll 8
        for (int f = 0; f < 64; f++) {
            float fv = fu[f];
            float2 wv = snw2[f * 32 + h2];
            acc.x += fv * wv.x;
            acc.y += fv * wv.y;
        }
        *(float2*)(out + ((size_t)b * N_NODES + n) * HID + 2 * h2) = acc;
    }
}

// ================= launch =================
extern "C" void kernel_launch(void* const* d_in, const int* in_sizes, int n_in,
                              void* d_out, int out_size) {
    const float* H    = (const float*)d_in[0];   // [64,1024,12,64]
    const float* G    = (const float*)d_in[1];   // [64,6,32]
    const float* L    = (const float*)d_in[2];   // [64,12,32]
    const float* Wq   = (const float*)d_in[3];   // [64,32]
    const float* bq   = (const float*)d_in[4];   // [32]
    const float* emb  = (const float*)d_in[5];   // [1024,16]
    const float* pool = (const float*)d_in[6];   // [16,64,64]
    float* out = (float*)d_out;                  // [64,1024,64]

    static bool attr_done = false;
    if (!attr_done) {
        cudaFuncSetAttribute(k1_tc, cudaFuncAttributeMaxDynamicSharedMemorySize, K1_SMEM);
        attr_done = true;
    }

    // k1_tc kept in captured launch slot 3.
    pA_kernel  <<<128, 256>>>(G, L, Wq);           // slot 0
    pAux_kernel<<<9, 256>>>(G, L, bq);             // slot 1
    pBsw_kernel<<<48, 256>>>();                    // slot 2
    k1_tc      <<<ROWS / 128, 256, K1_SMEM>>>(H);  // slot 3  <-- profiled
    k3_out     <<<N_NODES, 256>>>(emb, pool, out); // slot 4
}

// round 10
// speedup vs baseline: 1.2321x; 1.2321x over previous
#include <cuda_runtime.h>
#include <cuda_bf16.h>
#include <cstdint>

// ---------------- problem constants ----------------
#define B_BATCH 64
#define N_NODES 1024
#define S_LOC   12
#define HID     64
#define PAT     32
#define M_GLB   64
#define S_GLB   6
#define M_LOC   64
#define D_EMB   16
#define KDIM    768           // S_LOC * HID
#define CDIM    128           // M_LOC + M_GLB
#define ROWS    65536         // B_BATCH * N_NODES
#define NCHUNK  12            // K chunks of 64

// tcgen05 is arch-SPECIFIC: only emit its PTX in the sm_103a/sm_100a pass.
#if defined(__CUDA_ARCH_FEAT_SM103_ALL) || defined(__CUDA_ARCH_FEAT_SM100_ALL) || \
    (defined(__CUDA_ARCH_SPECIFIC__) && (__CUDA_ARCH_SPECIFIC__ == 1030 || __CUDA_ARCH_SPECIFIC__ == 1000))
#define HAS_TCGEN05 1
#else
#define HAS_TCGEN05 0
#endif

// ---------------- static device scratch ----------------
__device__ __align__(16) float g_A[KDIM * CDIM];           // folded weights  [768][128]
__device__ __align__(16) float g_bias[CDIM];
__device__ __align__(16) float g_Lm[M_LOC * PAT];
__device__ __align__(16) float g_Gm[M_GLB * PAT];
__device__ __align__(16) float g_nw[N_NODES * 64 * HID];   // [1024][64][64]
__device__ __align__(16) float g_sim[(size_t)ROWS * CDIM]; // logits [65536][128]
// pre-swizzled bf16 B operand (hi/lo), [chunk][128 n-rows][128 bytes]
__device__ __align__(16) unsigned char g_Bhi[NCHUNK * 128 * 128];
__device__ __align__(16) unsigned char g_Blo[NCHUNK * 128 * 128];

// ---------------- helpers legal on all targets ----------------
__device__ __forceinline__ uint32_t su32(const void* p) {
    uint32_t a;
    asm("{ .reg .u64 t; cvta.to.shared.u64 t, %1; cvt.u32.u64 %0, t; }" : "=r"(a) : "l"(p));
    return a;
}
__device__ __forceinline__ uint32_t bf16pack(float x0, float x1) {
    uint32_t r;
    asm("cvt.rn.bf16x2.f32 %0, %1, %2;" : "=r"(r) : "f"(x1), "f"(x0));
    return r;
}
__device__ __forceinline__ void bf16split(float x0, float x1, uint32_t& hi, uint32_t& lo) {
    hi = bf16pack(x0, x1);
    float h0 = __uint_as_float(hi << 16);
    float h1 = __uint_as_float(hi & 0xffff0000u);
    lo = bf16pack(x0 - h0, x1 - h1);
}
__device__ __forceinline__ void cp16(uint32_t saddr, const void* gaddr) {
    asm volatile("cp.async.cg.shared.global [%0], [%1], 16;" :: "r"(saddr), "l"(gaddr) : "memory");
}

#if HAS_TCGEN05
__device__ __forceinline__ uint32_t elect1() {
    uint32_t r;
    asm volatile("{ .reg .pred p; elect.sync _|p, 0xFFFFFFFF; selp.b32 %0, 1, 0, p; }" : "=r"(r));
    return r;
}
__device__ __forceinline__ uint64_t mkdesc(uint32_t saddr) {
    // SW128 K-major: layout=2, version=1, SBO=64, LBO=1
    return 0x4000404000010000ULL | ((uint64_t)(saddr >> 4) & 0x3FFF);
}
__device__ __forceinline__ void mma_f16_ss(uint32_t d, uint64_t ad, uint64_t bd,
                                           uint32_t idesc, uint32_t en) {
    asm volatile(
        "{\n\t.reg .pred p;\n\tsetp.ne.u32 p, %4, 0;\n\t"
        "tcgen05.mma.cta_group::1.kind::f16 [%0], %1, %2, %3, {%5, %5, %5, %5}, p;\n\t}"
        :: "r"(d), "l"(ad), "l"(bd), "r"(idesc), "r"(en), "r"(0u) : "memory");
}
#define MBAR_INIT(a, n) asm volatile("mbarrier.init.shared.b64 [%0], %1;" :: "r"(a), "r"(n) : "memory")
#define MBAR_WAITP(addr, par) do {                                                      \
    uint32_t _m = (addr), _p = (par), _d;                                               \
    asm volatile("{\n\t.reg .pred p;\n\t"                                               \
        "mbarrier.try_wait.parity.acquire.cta.shared::cta.b64 p, [%1], %2;\n\t"         \
        "selp.b32 %0, 1, 0, p;\n\t}" : "=r"(_d) : "r"(_m), "r"(_p) : "memory");         \
    if (!_d) {                                                                          \
        asm volatile("{\n\t.reg .pred P1;\n\tWL_%=:\n\t"                                \
            "mbarrier.try_wait.parity.acquire.cta.shared::cta.b64 P1, [%0], %1, 0x989680;\n\t" \
            "@P1 bra.uni WD_%=;\n\tbra.uni WL_%=;\n\tWD_%=:\n\t}"                       \
            :: "r"(_m), "r"(_p) : "memory");                                            \
    }                                                                                   \
} while (0)
#define TC_COMMIT(a) asm volatile("tcgen05.commit.cta_group::1.mbarrier::arrive::one.shared::cluster.b64 [%0];" :: "r"(a) : "memory")
#define TC_WAITLD()  asm volatile("tcgen05.wait::ld.sync.aligned;" ::: "memory")
#define LDTM32(r, a) asm volatile(                                                      \
    "tcgen05.ld.sync.aligned.32x32b.x32.b32 "                                           \
    "{%0, %1, %2, %3, %4, %5, %6, %7, %8, %9, %10, %11, %12, %13, %14, %15, "           \
    " %16, %17, %18, %19, %20, %21, %22, %23, %24, %25, %26, %27, %28, %29, %30, %31}, [%32];" \
    : "=r"((r)[0]), "=r"((r)[1]), "=r"((r)[2]), "=r"((r)[3]),                           \
      "=r"((r)[4]), "=r"((r)[5]), "=r"((r)[6]), "=r"((r)[7]),                           \
      "=r"((r)[8]), "=r"((r)[9]), "=r"((r)[10]), "=r"((r)[11]),                         \
      "=r"((r)[12]), "=r"((r)[13]), "=r"((r)[14]), "=r"((r)[15]),                       \
      "=r"((r)[16]), "=r"((r)[17]), "=r"((r)[18]), "=r"((r)[19]),                       \
      "=r"((r)[20]), "=r"((r)[21]), "=r"((r)[22]), "=r"((r)[23]),                       \
      "=r"((r)[24]), "=r"((r)[25]), "=r"((r)[26]), "=r"((r)[27]),                       \
      "=r"((r)[28]), "=r"((r)[29]), "=r"((r)[30]), "=r"((r)[31])                        \
    : "r"(a))
// idesc: fp32 accum, bf16 x bf16, M=128, N=128, K-major both
#define IDESC_BF16 0x8200490u
#endif  // HAS_TCGEN05

// ================= P1: A[k][c] = folded bank weights (coalesced) =================
__global__ __launch_bounds__(256) void pA_kernel(const float* __restrict__ G,
                                                 const float* __restrict__ L,
                                                 const float* __restrict__ Wq) {
    __shared__ float sBank[S_LOC * PAT];
    __shared__ float sWq[HID][PAT + 1];
    int c = blockIdx.x, tid = threadIdx.x;
    #pragma unroll
    for (int i = tid; i < HID * PAT; i += 256) sWq[i >> 5][i & 31] = Wq[i];
    if (c < 64) {
        if (tid < S_LOC * PAT) sBank[tid] = L[c * (S_LOC * PAT) + tid];
        if (tid + 256 < S_LOC * PAT) sBank[tid + 256] = L[c * (S_LOC * PAT) + tid + 256];
    } else {
        if (tid < S_GLB * PAT) sBank[tid] = G[(c - 64) * (S_GLB * PAT) + tid];
    }
    __syncthreads();
    float scale = (c < 64) ? 1.0f : 0.5f;
    #pragma unroll
    for (int j = 0; j < 3; j++) {
        int k = j * 256 + tid;
        int s = k >> 6, h = k & 63;
        int base = (c < 64) ? s * PAT : (s >> 1) * PAT;
        float v = 0.f;
        #pragma unroll
        for (int p = 0; p < PAT; p++) v += sWq[h][p] * sBank[base + p];
        g_A[k * CDIM + c] = v * scale;
    }
}

// ================= P2: bias + bank means fused =================
__global__ void pAux_kernel(const float* __restrict__ G, const float* __restrict__ L,
                            const float* __restrict__ bq) {
    if (blockIdx.x == 0) {
        int c = threadIdx.x;
        if (c >= 128) return;
        float v = 0.f;
        if (c < 64) {
            for (int s = 0; s < S_LOC; s++)
                #pragma unroll
                for (int p = 0; p < PAT; p++) v += bq[p] * L[c * (S_LOC * PAT) + s * PAT + p];
        } else {
            for (int s = 0; s < S_GLB; s++)
                #pragma unroll
                for (int p = 0; p < PAT; p++) v += bq[p] * G[(c - 64) * (S_GLB * PAT) + s * PAT + p];
        }
        g_bias[c] = v;
    } else {
        int idx = (blockIdx.x - 1) * 256 + threadIdx.x;
        if (idx >= 2048) return;
        int m = idx >> 5, p = idx & 31;
        float lm = 0.f, gm = 0.f;
        for (int s = 0; s < S_LOC; s++) lm += L[m * (S_LOC * PAT) + s * PAT + p];
        for (int s = 0; s < S_GLB; s++) gm += G[m * (S_GLB * PAT) + s * PAT + p];
        g_Lm[idx] = lm * (1.f / 12.f);
        g_Gm[idx] = gm * (1.f / 6.f);
    }
}

// ================= P3: pre-swizzled bf16 hi/lo split of B = g_A^T =================
__global__ void pBsw_kernel() {
    int t = blockIdx.x * 256 + threadIdx.x;          // < 12288
    int ci = t >> 10;
    int kq = (t >> 7) & 7;
    int n  = t & 127;                                // lane-fastest: coalesced g_A reads
    uint32_t hi[4], lo[4];
    #pragma unroll
    for (int p = 0; p < 4; p++) {
        int k0 = ci * 64 + kq * 8 + 2 * p;
        float x0 = g_A[(k0 + 0) * CDIM + n];
        float x1 = g_A[(k0 + 1) * CDIM + n];
        bf16split(x0, x1, hi[p], lo[p]);
    }
    int off = n * 128 + kq * 16;
    int swo = off ^ ((off >> 3) & 0x70);
    *(uint4*)(g_Bhi + ci * 16384 + swo) = make_uint4(hi[0], hi[1], hi[2], hi[3]);
    *(uint4*)(g_Blo + ci * 16384 + swo) = make_uint4(lo[0], lo[1], lo[2], lo[3]);
}

// ================= K1: tcgen05 bf16x3 GEMM: g_sim = H @ g_A + bias =================
// SINGLE-STAGE ring, 66.5 KB smem -> 3 CTAs/SM (cross-CTA overlap hides latency).
// TMEM: 3 CTAs x 128 cols = 384 <= 512. Race-free alloc: warp 0 allocs, THEN
// relinquishes (no other warp touches the allocator).
// smem: [0..4) tmem ptr, [16..24) mbarrier, [64..576) bias,
//       [1024..66560) stage: Ahi(16K) Alo(16K) Bhi(16K) Blo(16K)
#define K1_SMEM (1024 + 65536)
__global__ __launch_bounds__(256) void k1_tc(const float* __restrict__ H) {
#if HAS_TCGEN05
    extern __shared__ __align__(1024) char smem[];
    const int tid = threadIdx.x, w = tid >> 5, lane = tid & 31;
    const int row0 = blockIdx.x << 7;
    uint32_t sb = su32(smem);

    if (w == 0) {
        asm volatile("tcgen05.alloc.cta_group::1.sync.aligned.shared::cta.b32 [%0], %1;"
                     :: "r"(sb), "r"(128u) : "memory");
        asm volatile("tcgen05.relinquish_alloc_permit.cta_group::1.sync.aligned;");
    }
    if (tid == 0) MBAR_INIT(sb + 16, 1);
    float* sbias = (float*)(smem + 64);
    if (tid < 128) sbias[tid] = g_bias[tid];
    __syncthreads();
    uint32_t tmem;
    asm("ld.shared.b32 %0, [%1];" : "=r"(tmem) : "r"(sb));

    char* buf = smem + 1024;
    const uint32_t bufb = sb + 1024;

    for (int c = 0; c < NCHUNK; c++) {
        // wait for previous chunk's MMA before overwriting the single stage
        if (c > 0) MBAR_WAITP(sb + 16, (uint32_t)((c - 1) & 1));

        // stage B via cp.async (pre-swizzled)
        {
            const char* bh = (const char*)g_Bhi + c * 16384 + tid * 16;
            const char* bl = (const char*)g_Blo + c * 16384 + tid * 16;
            uint32_t dh = bufb + 32768 + tid * 16;
            uint32_t dl = bufb + 49152 + tid * 16;
            #pragma unroll
            for (int i = 0; i < 4; i++) {
                cp16(dh + i * 4096, bh + i * 4096);
                cp16(dl + i * 4096, bl + i * 4096);
            }
            asm volatile("cp.async.commit_group;" ::: "memory");
        }
        // stage A: load H fp32, split hi/lo, swizzled STS
        #pragma unroll
        for (int it = 0; it < 4; it++) {
            int task = it * 256 + tid;
            int r = task >> 3, kq = task & 7;
            const float* hp = H + (size_t)(row0 + r) * KDIM + c * 64 + kq * 8;
            float4 u0 = *(const float4*)hp;
            float4 u1 = *(const float4*)(hp + 4);
            uint32_t hi[4], lo[4];
            bf16split(u0.x, u0.y, hi[0], lo[0]);
            bf16split(u0.z, u0.w, hi[1], lo[1]);
            bf16split(u1.x, u1.y, hi[2], lo[2]);
            bf16split(u1.z, u1.w, hi[3], lo[3]);
            int off = r * 128 + kq * 16;
            int swo = off ^ ((off >> 3) & 0x70);
            *(uint4*)(buf + swo)         = make_uint4(hi[0], hi[1], hi[2], hi[3]);
            *(uint4*)(buf + 16384 + swo) = make_uint4(lo[0], lo[1], lo[2], lo[3]);
        }
        asm volatile("cp.async.wait_group 0;" ::: "memory");
        asm volatile("fence.proxy.async.shared::cta;" ::: "memory");
        __syncthreads();

        if (w == 0 && elect1()) {
            uint64_t ah = mkdesc(bufb);
            uint64_t al = mkdesc(bufb + 16384);
            uint64_t bh = mkdesc(bufb + 32768);
            uint64_t bl = mkdesc(bufb + 49152);
            #pragma unroll
            for (int ks = 0; ks < 4; ks++) {
                uint32_t en0 = (c == 0 && ks == 0) ? 0u : 1u;
                mma_f16_ss(tmem, ah + 2 * ks, bh + 2 * ks, IDESC_BF16, en0);
                mma_f16_ss(tmem, ah + 2 * ks, bl + 2 * ks, IDESC_BF16, 1u);
                mma_f16_ss(tmem, al + 2 * ks, bh + 2 * ks, IDESC_BF16, 1u);
            }
            TC_COMMIT(sb + 16);
        }
    }

    // final chunk (c=11, 12th arrival): parity 11&1 = 1
    MBAR_WAITP(sb + 16, 1u);
    asm volatile("tcgen05.fence::after_thread_sync;" ::: "memory");

    if (w < 4) {
        #pragma unroll
        for (int base = 0; base < 128; base += 32) {
            uint32_t dr[32];
            LDTM32(dr, tmem + base);
            TC_WAITLD();
            float* op = g_sim + (size_t)(row0 + w * 32 + lane) * CDIM + base;
            #pragma unroll
            for (int j = 0; j < 32; j += 4) {
                float4 o;
                o.x = __uint_as_float(dr[j + 0]) + sbias[base + j + 0];
                o.y = __uint_as_float(dr[j + 1]) + sbias[base + j + 1];
                o.z = __uint_as_float(dr[j + 2]) + sbias[base + j + 2];
                o.w = __uint_as_float(dr[j + 3]) + sbias[base + j + 3];
                *(float4*)(op + j) = o;
            }
        }
        asm volatile("tcgen05.fence::before_thread_sync;" ::: "memory");
    }
    __syncthreads();
    if (w == 0) {
        asm volatile("tcgen05.dealloc.cta_group::1.sync.aligned.b32 %0, %1;"
                     :: "r"(tmem), "r"(128u));
    }
#else
    // Generic-arch fallback (never executed on sm_103a; keeps compute_103 PTX legal).
    extern __shared__ __align__(1024) char smem[];
    float (*As)[128] = (float(*)[128])smem;            // [16][128]
    float (*Bs)[128] = (float(*)[128])(smem + 8192);   // [16][128]
    int tid = threadIdx.x;
    int row0 = blockIdx.x << 7;
    int ty = tid >> 4, tx = tid & 15;
    float acc[8][8] = {};
    const float* Hb = H + (size_t)row0 * KDIM;
    for (int kt = 0; kt < KDIM; kt += 16) {
        #pragma unroll
        for (int i = 0; i < 2; i++) {
            int id = tid + i * 256;
            int m = id >> 2, kk = (id & 3) << 2;
            float4 v = *(const float4*)(Hb + (size_t)m * KDIM + kt + kk);
            As[kk + 0][m] = v.x; As[kk + 1][m] = v.y;
            As[kk + 2][m] = v.z; As[kk + 3][m] = v.w;
        }
        #pragma unroll
        for (int i = 0; i < 2; i++) {
            int id = tid + i * 256;
            int k = id >> 5, n4 = (id & 31) << 2;
            *(float4*)&Bs[k][n4] = *(const float4*)(g_A + (kt + k) * CDIM + n4);
        }
        __syncthreads();
        #pragma unroll
        for (int k = 0; k < 16; k++) {
            float a[8], b[8];
            #pragma unroll
            for (int i = 0; i < 8; i++) a[i] = As[k][ty * 8 + i];
            #pragma unroll
            for (int j = 0; j < 8; j++) b[j] = Bs[k][tx * 8 + j];
            #pragma unroll
            for (int i = 0; i < 8; i++)
                #pragma unroll
                for (int j = 0; j < 8; j++) acc[i][j] += a[i] * b[j];
        }
        __syncthreads();
    }
    #pragma unroll
    for (int i = 0; i < 8; i++) {
        size_t r = row0 + ty * 8 + i;
        float* op = g_sim + r * CDIM + tx * 8;
        #pragma unroll
        for (int j = 0; j < 8; j++) op[j] = acc[i][j] + g_bias[tx * 8 + j];
    }
#endif
}

// ================= P5: node_w = emb @ pool (4 nodes/block, float4 ILP) =================
__global__ __launch_bounds__(256) void pNw_kernel(const float* __restrict__ emb,
                                                  const float* __restrict__ pool) {
    __shared__ float se[4][16];
    int n0 = blockIdx.x << 2, tid = threadIdx.x;
    if (tid < 64) se[tid >> 4][tid & 15] = emb[(n0 + (tid >> 4)) * D_EMB + (tid & 15)];
    __syncthreads();
    float e0[16], e1[16], e2[16], e3[16];
    #pragma unroll
    for (int d = 0; d < 16; d++) {
        e0[d] = se[0][d]; e1[d] = se[1][d]; e2[d] = se[2][d]; e3[d] = se[3][d];
    }
    const float4* p4 = (const float4*)pool;
    #pragma unroll
    for (int j = 0; j < 4; j++) {
        int o = j * 256 + tid;
        float4 a0 = {0, 0, 0, 0}, a1 = a0, a2 = a0, a3 = a0;
        #pragma unroll
        for (int d = 0; d < 16; d++) {
            float4 pv = p4[d * 1024 + o];
            a0.x += e0[d] * pv.x; a0.y += e0[d] * pv.y; a0.z += e0[d] * pv.z; a0.w += e0[d] * pv.w;
            a1.x += e1[d] * pv.x; a1.y += e1[d] * pv.y; a1.z += e1[d] * pv.z; a1.w += e1[d] * pv.w;
            a2.x += e2[d] * pv.x; a2.y += e2[d] * pv.y; a2.z += e2[d] * pv.z; a2.w += e2[d] * pv.w;
            a3.x += e3[d] * pv.x; a3.y += e3[d] * pv.y; a3.z += e3[d] * pv.z; a3.w += e3[d] * pv.w;
        }
        float4* nw4 = (float4*)g_nw;
        nw4[(size_t)(n0 + 0) * 1024 + o] = a0;
        nw4[(size_t)(n0 + 1) * 1024 + o] = a1;
        nw4[(size_t)(n0 + 2) * 1024 + o] = a2;
        nw4[(size_t)(n0 + 3) * 1024 + o] = a3;
    }
}

// ================= K2: softmax + context + per-node projection (R6-proven) =================
__global__ __launch_bounds__(256) void k2_epi(float* __restrict__ out) {
    __shared__ float snw[64][64];
    __shared__ float sLm[64][32];
    __shared__ float sGm[64][32];
    __shared__ float sattn[8][128];
    __shared__ float sfused[8][64];

    int n = blockIdx.x, tid = threadIdx.x;
    int w = tid >> 5, lane = tid & 31;

    {
        const float4* src = (const float4*)(g_nw + (size_t)n * 4096);
        float4* dst = (float4*)&snw[0][0];
        #pragma unroll
        for (int i = 0; i < 4; i++) dst[tid + i * 256] = src[tid + i * 256];
        float* lm = &sLm[0][0]; float* gm = &sGm[0][0];
        for (int i = tid; i < 2048; i += 256) { lm[i] = g_Lm[i]; gm[i] = g_Gm[i]; }
    }
    __syncthreads();

    for (int i = 0; i < 8; i++) {
        int b = i * 8 + w;
        size_t row = (size_t)b * N_NODES + n;
        const float* sp = g_sim + row * CDIM;
        float v0 = sp[lane], v1 = sp[lane + 32];
        float v2 = sp[lane + 64], v3 = sp[lane + 96];

        float mx = fmaxf(v0, v1);
        #pragma unroll
        for (int o = 16; o; o >>= 1) mx = fmaxf(mx, __shfl_xor_sync(0xffffffffu, mx, o));
        float e0 = __expf(v0 - mx), e1 = __expf(v1 - mx);
        float s = e0 + e1;
        #pragma unroll
        for (int o = 16; o; o >>= 1) s += __shfl_xor_sync(0xffffffffu, s, o);
        float inv = 1.f / s;
        sattn[w][lane] = e0 * inv; sattn[w][lane + 32] = e1 * inv;

        mx = fmaxf(v2, v3);
        #pragma unroll
        for (int o = 16; o; o >>= 1) mx = fmaxf(mx, __shfl_xor_sync(0xffffffffu, mx, o));
        float e2 = __expf(v2 - mx), e3 = __expf(v3 - mx);
        s = e2 + e3;
        #pragma unroll
        for (int o = 16; o; o >>= 1) s += __shfl_xor_sync(0xffffffffu, s, o);
        inv = 1.f / s;
        sattn[w][64 + lane] = e2 * inv; sattn[w][96 + lane] = e3 * inv;
        __syncwarp();

        float lctx = 0.f, gctx = 0.f;
        #pragma unroll 8
        for (int m = 0; m < 64; m++) {
            lctx += sattn[w][m]      * sLm[m][lane];
            gctx += sattn[w][64 + m] * sGm[m][lane];
        }
        sfused[w][lane] = lctx; sfused[w][lane + 32] = gctx;
        __syncwarp();

        float o0 = 0.f, o1 = 0.f;
        #pragma unroll 8
        for (int f = 0; f < 64; f++) {
            float fv = sfused[w][f];
            o0 += fv * snw[f][lane];
            o1 += fv * snw[f][lane + 32];
        }
        float* op = out + row * HID;
        op[lane] = o0; op[lane + 32] = o1;
        __syncwarp();
    }
}

// ================= launch =================
extern "C" void kernel_launch(void* const* d_in, const int* in_sizes, int n_in,
                              void* d_out, int out_size) {
    const float* H    = (const float*)d_in[0];   // [64,1024,12,64]
    const float* G    = (const float*)d_in[1];   // [64,6,32]
    const float* L    = (const float*)d_in[2];   // [64,12,32]
    const float* Wq   = (const float*)d_in[3];   // [64,32]
    const float* bq   = (const float*)d_in[4];   // [32]
    const float* emb  = (const float*)d_in[5];   // [1024,16]
    const float* pool = (const float*)d_in[6];   // [16,64,64]
    float* out = (float*)d_out;                  // [64,1024,64]

    static bool attr_done = false;
    if (!attr_done) {
        cudaFuncSetAttribute(k1_tc, cudaFuncAttributeMaxDynamicSharedMemorySize, K1_SMEM);
        attr_done = true;
    }

    // k1_tc kept in captured launch slot 3.
    pA_kernel  <<<128, 256>>>(G, L, Wq);           // slot 0
    pAux_kernel<<<9, 256>>>(G, L, bq);             // slot 1
    pBsw_kernel<<<48, 256>>>();                    // slot 2
    k1_tc      <<<ROWS / 128, 256, K1_SMEM>>>(H);  // slot 3  <-- profiled
    pNw_kernel <<<256, 256>>>(emb, pool);          // slot 4
    k2_epi     <<<N_NODES, 256>>>(out);            // slot 5
}

// round 12
// speedup vs baseline: 1.2719x; 1.0323x over previous
#include <cuda_runtime.h>
#include <cuda_bf16.h>
#include <cstdint>

// ---------------- problem constants ----------------
#define B_BATCH 64
#define N_NODES 1024
#define S_LOC   12
#define HID     64
#define PAT     32
#define M_GLB   64
#define S_GLB   6
#define M_LOC   64
#define D_EMB   16
#define KDIM    768           // S_LOC * HID
#define CDIM    128           // M_LOC + M_GLB
#define ROWS    65536         // B_BATCH * N_NODES
#define NCHUNK  12            // K chunks of 64

// tcgen05 is arch-SPECIFIC: only emit its PTX in the sm_103a/sm_100a pass.
#if defined(__CUDA_ARCH_FEAT_SM103_ALL) || defined(__CUDA_ARCH_FEAT_SM100_ALL) || \
    (defined(__CUDA_ARCH_SPECIFIC__) && (__CUDA_ARCH_SPECIFIC__ == 1030 || __CUDA_ARCH_SPECIFIC__ == 1000))
#define HAS_TCGEN05 1
#else
#define HAS_TCGEN05 0
#endif

// ---------------- static device scratch ----------------
__device__ __align__(16) float g_A[KDIM * CDIM];           // only used by generic fallback
__device__ __align__(16) float g_bias[CDIM];
__device__ __align__(16) float g_Lm[M_LOC * PAT];
__device__ __align__(16) float g_Gm[M_GLB * PAT];
__device__ __align__(16) float g_nw[N_NODES * 64 * HID];   // [1024][64][64]
__device__ __align__(16) float g_sim[(size_t)ROWS * CDIM]; // logits [65536][128]
// pre-swizzled bf16 B operand (hi/lo), [chunk][128 n-rows][128 bytes]
__device__ __align__(16) unsigned char g_Bhi[NCHUNK * 128 * 128];
__device__ __align__(16) unsigned char g_Blo[NCHUNK * 128 * 128];

// ---------------- helpers legal on all targets ----------------
__device__ __forceinline__ uint32_t su32(const void* p) {
    uint32_t a;
    asm("{ .reg .u64 t; cvta.to.shared.u64 t, %1; cvt.u32.u64 %0, t; }" : "=r"(a) : "l"(p));
    return a;
}
__device__ __forceinline__ uint32_t bf16pack(float x0, float x1) {
    uint32_t r;
    asm("cvt.rn.bf16x2.f32 %0, %1, %2;" : "=r"(r) : "f"(x1), "f"(x0));
    return r;
}
__device__ __forceinline__ void bf16split(float x0, float x1, uint32_t& hi, uint32_t& lo) {
    hi = bf16pack(x0, x1);
    float h0 = __uint_as_float(hi << 16);
    float h1 = __uint_as_float(hi & 0xffff0000u);
    lo = bf16pack(x0 - h0, x1 - h1);
}
__device__ __forceinline__ void cp16(uint32_t saddr, const void* gaddr) {
    asm volatile("cp.async.cg.shared.global [%0], [%1], 16;" :: "r"(saddr), "l"(gaddr) : "memory");
}

#if HAS_TCGEN05
__device__ __forceinline__ uint32_t elect1() {
    uint32_t r;
    asm volatile("{ .reg .pred p; elect.sync _|p, 0xFFFFFFFF; selp.b32 %0, 1, 0, p; }" : "=r"(r));
    return r;
}
__device__ __forceinline__ uint64_t mkdesc(uint32_t saddr) {
    // SW128 K-major: layout=2, version=1, SBO=64, LBO=1
    return 0x4000404000010000ULL | ((uint64_t)(saddr >> 4) & 0x3FFF);
}
__device__ __forceinline__ void mma_f16_ss(uint32_t d, uint64_t ad, uint64_t bd,
                                           uint32_t idesc, uint32_t en) {
    asm volatile(
        "{\n\t.reg .pred p;\n\tsetp.ne.u32 p, %4, 0;\n\t"
        "tcgen05.mma.cta_group::1.kind::f16 [%0], %1, %2, %3, {%5, %5, %5, %5}, p;\n\t}"
        :: "r"(d), "l"(ad), "l"(bd), "r"(idesc), "r"(en), "r"(0u) : "memory");
}
#define MBAR_INIT(a, n) asm volatile("mbarrier.init.shared.b64 [%0], %1;" :: "r"(a), "r"(n) : "memory")
#define MBAR_WAITP(addr, par) do {                                                      \
    uint32_t _m = (addr), _p = (par), _d;                                               \
    asm volatile("{\n\t.reg .pred p;\n\t"                                               \
        "mbarrier.try_wait.parity.acquire.cta.shared::cta.b64 p, [%1], %2;\n\t"         \
        "selp.b32 %0, 1, 0, p;\n\t}" : "=r"(_d) : "r"(_m), "r"(_p) : "memory");         \
    if (!_d) {                                                                          \
        asm volatile("{\n\t.reg .pred P1;\n\tWL_%=:\n\t"                                \
            "mbarrier.try_wait.parity.acquire.cta.shared::cta.b64 P1, [%0], %1, 0x989680;\n\t" \
            "@P1 bra.uni WD_%=;\n\tbra.uni WL_%=;\n\tWD_%=:\n\t}"                       \
            :: "r"(_m), "r"(_p) : "memory");                                            \
    }                                                                                   \
} while (0)
#define TC_COMMIT(a) asm volatile("tcgen05.commit.cta_group::1.mbarrier::arrive::one.shared::cluster.b64 [%0];" :: "r"(a) : "memory")
#define TC_WAITLD()  asm volatile("tcgen05.wait::ld.sync.aligned;" ::: "memory")
#define LDTM32(r, a) asm volatile(                                                      \
    "tcgen05.ld.sync.aligned.32x32b.x32.b32 "                                           \
    "{%0, %1, %2, %3, %4, %5, %6, %7, %8, %9, %10, %11, %12, %13, %14, %15, "           \
    " %16, %17, %18, %19, %20, %21, %22, %23, %24, %25, %26, %27, %28, %29, %30, %31}, [%32];" \
    : "=r"((r)[0]), "=r"((r)[1]), "=r"((r)[2]), "=r"((r)[3]),                           \
      "=r"((r)[4]), "=r"((r)[5]), "=r"((r)[6]), "=r"((r)[7]),                           \
      "=r"((r)[8]), "=r"((r)[9]), "=r"((r)[10]), "=r"((r)[11]),                         \
      "=r"((r)[12]), "=r"((r)[13]), "=r"((r)[14]), "=r"((r)[15]),                       \
      "=r"((r)[16]), "=r"((r)[17]), "=r"((r)[18]), "=r"((r)[19]),                       \
      "=r"((r)[20]), "=r"((r)[21]), "=r"((r)[22]), "=r"((r)[23]),                       \
      "=r"((r)[24]), "=r"((r)[25]), "=r"((r)[26]), "=r"((r)[27]),                       \
      "=r"((r)[28]), "=r"((r)[29]), "=r"((r)[30]), "=r"((r)[31])                        \
    : "r"(a))
// idesc: fp32 accum, bf16 x bf16, M=128, N=128, K-major both
#define IDESC_BF16 0x8200490u
#endif  // HAS_TCGEN05

// ================= P0: pFold — folded-weight split/swizzle + bias + means =================
// blocks 0-11: chunk ci -> g_Bhi/g_Blo directly (A never hits DRAM).
//   chunk ci covers k in [64ci, 64ci+64) => s = ci (local) / ci>>1 (global slice).
// block 12: bias + bank means.
__global__ __launch_bounds__(256) void pFold_kernel(const float* __restrict__ G,
                                                    const float* __restrict__ L,
                                                    const float* __restrict__ Wq,
                                                    const float* __restrict__ bq) {
    int blk = blockIdx.x, tid = threadIdx.x;
    if (blk < 12) {
        __shared__ float sWq[64][36];   // padded rows, float4-aligned (36*4=144B)
        __shared__ float sBl[64][36];   // local bank slice  L[c][ci][:]
        __shared__ float sBg[64][36];   // global bank slice G[c][ci/2][:]
        int ci = blk;
        for (int i = tid; i < 64 * 32; i += 256) sWq[i >> 5][i & 31] = Wq[i];
        for (int i = tid; i < 2048; i += 256) {
            int c = i >> 5, p = i & 31;
            sBl[c][p] = L[c * (S_LOC * PAT) + ci * PAT + p];
            sBg[c][p] = G[c * (S_GLB * PAT) + (ci >> 1) * PAT + p];
        }
        __syncthreads();
        #pragma unroll
        for (int it = 0; it < 4; it++) {
            int task = it * 256 + tid;               // < 1024
            int kq = (task >> 7) & 7;
            int n  = task & 127;
            const float* bank = (n < 64) ? &sBl[n][0] : &sBg[n - 64][0];
            float scale = (n < 64) ? 1.0f : 0.5f;
            uint32_t hi[4], lo[4];
            #pragma unroll
            for (int p2 = 0; p2 < 4; p2++) {
                int h0 = kq * 8 + 2 * p2;
                float x0 = 0.f, x1 = 0.f;
                #pragma unroll
                for (int p = 0; p < 32; p++) {
                    float bp = bank[p];
                    x0 += sWq[h0][p] * bp;
                    x1 += sWq[h0 + 1][p] * bp;
                }
                bf16split(x0 * scale, x1 * scale, hi[p2], lo[p2]);
            }
            int off = n * 128 + kq * 16;
            int swo = off ^ ((off >> 3) & 0x70);
            *(uint4*)(g_Bhi + ci * 16384 + swo) = make_uint4(hi[0], hi[1], hi[2], hi[3]);
            *(uint4*)(g_Blo + ci * 16384 + swo) = make_uint4(lo[0], lo[1], lo[2], lo[3]);
        }
    } else {
        // bias
        if (tid < 128) {
            int c = tid;
            float v = 0.f;
            if (c < 64) {
                for (int s = 0; s < S_LOC; s++)
                    #pragma unroll
                    for (int p = 0; p < PAT; p++) v += bq[p] * L[c * (S_LOC * PAT) + s * PAT + p];
            } else {
                for (int s = 0; s < S_GLB; s++)
                    #pragma unroll
                    for (int p = 0; p < PAT; p++) v += bq[p] * G[(c - 64) * (S_GLB * PAT) + s * PAT + p];
            }
            g_bias[c] = v;
        }
        // means
        for (int idx = tid; idx < 2048; idx += 256) {
            int m = idx >> 5, p = idx & 31;
            float lm = 0.f, gm = 0.f;
            for (int s = 0; s < S_LOC; s++) lm += L[m * (S_LOC * PAT) + s * PAT + p];
            for (int s = 0; s < S_GLB; s++) gm += G[m * (S_GLB * PAT) + s * PAT + p];
            g_Lm[idx] = lm * (1.f / 12.f);
            g_Gm[idx] = gm * (1.f / 6.f);
        }
    }
}

// ================= P1: node_w = emb @ pool (4 nodes/block, float4 ILP) =================
__global__ __launch_bounds__(256) void pNw_kernel(const float* __restrict__ emb,
                                                  const float* __restrict__ pool) {
    __shared__ float se[4][16];
    int n0 = blockIdx.x << 2, tid = threadIdx.x;
    if (tid < 64) se[tid >> 4][tid & 15] = emb[(n0 + (tid >> 4)) * D_EMB + (tid & 15)];
    __syncthreads();
    float e0[16], e1[16], e2[16], e3[16];
    #pragma unroll
    for (int d = 0; d < 16; d++) {
        e0[d] = se[0][d]; e1[d] = se[1][d]; e2[d] = se[2][d]; e3[d] = se[3][d];
    }
    const float4* p4 = (const float4*)pool;
    #pragma unroll
    for (int j = 0; j < 4; j++) {
        int o = j * 256 + tid;
        float4 a0 = {0, 0, 0, 0}, a1 = a0, a2 = a0, a3 = a0;
        #pragma unroll
        for (int d = 0; d < 16; d++) {
            float4 pv = p4[d * 1024 + o];
            a0.x += e0[d] * pv.x; a0.y += e0[d] * pv.y; a0.z += e0[d] * pv.z; a0.w += e0[d] * pv.w;
            a1.x += e1[d] * pv.x; a1.y += e1[d] * pv.y; a1.z += e1[d] * pv.z; a1.w += e1[d] * pv.w;
            a2.x += e2[d] * pv.x; a2.y += e2[d] * pv.y; a2.z += e2[d] * pv.z; a2.w += e2[d] * pv.w;
            a3.x += e3[d] * pv.x; a3.y += e3[d] * pv.y; a3.z += e3[d] * pv.z; a3.w += e3[d] * pv.w;
        }
        float4* nw4 = (float4*)g_nw;
        nw4[(size_t)(n0 + 0) * 1024 + o] = a0;
        nw4[(size_t)(n0 + 1) * 1024 + o] = a1;
        nw4[(size_t)(n0 + 2) * 1024 + o] = a2;
        nw4[(size_t)(n0 + 3) * 1024 + o] = a3;
    }
}

// ================= K1: tcgen05 bf16x3 GEMM (R10-proven, unchanged) =================
#define K1_SMEM (1024 + 65536)
__global__ __launch_bounds__(256) void k1_tc(const float* __restrict__ H) {
#if HAS_TCGEN05
    extern __shared__ __align__(1024) char smem[];
    const int tid = threadIdx.x, w = tid >> 5, lane = tid & 31;
    const int row0 = blockIdx.x << 7;
    uint32_t sb = su32(smem);

    if (w == 0) {
        asm volatile("tcgen05.alloc.cta_group::1.sync.aligned.shared::cta.b32 [%0], %1;"
                     :: "r"(sb), "r"(128u) : "memory");
        asm volatile("tcgen05.relinquish_alloc_permit.cta_group::1.sync.aligned;");
    }
    if (tid == 0) MBAR_INIT(sb + 16, 1);
    float* sbias = (float*)(smem + 64);
    if (tid < 128) sbias[tid] = g_bias[tid];
    __syncthreads();
    uint32_t tmem;
    asm("ld.shared.b32 %0, [%1];" : "=r"(tmem) : "r"(sb));

    char* buf = smem + 1024;
    const uint32_t bufb = sb + 1024;

    for (int c = 0; c < NCHUNK; c++) {
        if (c > 0) MBAR_WAITP(sb + 16, (uint32_t)((c - 1) & 1));

        {
            const char* bh = (const char*)g_Bhi + c * 16384 + tid * 16;
            const char* bl = (const char*)g_Blo + c * 16384 + tid * 16;
            uint32_t dh = bufb + 32768 + tid * 16;
            uint32_t dl = bufb + 49152 + tid * 16;
            #pragma unroll
            for (int i = 0; i < 4; i++) {
                cp16(dh + i * 4096, bh + i * 4096);
                cp16(dl + i * 4096, bl + i * 4096);
            }
            asm volatile("cp.async.commit_group;" ::: "memory");
        }
        #pragma unroll
        for (int it = 0; it < 4; it++) {
            int task = it * 256 + tid;
            int r = task >> 3, kq = task & 7;
            const float* hp = H + (size_t)(row0 + r) * KDIM + c * 64 + kq * 8;
            float4 u0 = *(const float4*)hp;
            float4 u1 = *(const float4*)(hp + 4);
            uint32_t hi[4], lo[4];
            bf16split(u0.x, u0.y, hi[0], lo[0]);
            bf16split(u0.z, u0.w, hi[1], lo[1]);
            bf16split(u1.x, u1.y, hi[2], lo[2]);
            bf16split(u1.z, u1.w, hi[3], lo[3]);
            int off = r * 128 + kq * 16;
            int swo = off ^ ((off >> 3) & 0x70);
            *(uint4*)(buf + swo)         = make_uint4(hi[0], hi[1], hi[2], hi[3]);
            *(uint4*)(buf + 16384 + swo) = make_uint4(lo[0], lo[1], lo[2], lo[3]);
        }
        asm volatile("cp.async.wait_group 0;" ::: "memory");
        asm volatile("fence.proxy.async.shared::cta;" ::: "memory");
        __syncthreads();

        if (w == 0 && elect1()) {
            uint64_t ah = mkdesc(bufb);
            uint64_t al = mkdesc(bufb + 16384);
            uint64_t bh = mkdesc(bufb + 32768);
            uint64_t bl = mkdesc(bufb + 49152);
            #pragma unroll
            for (int ks = 0; ks < 4; ks++) {
                uint32_t en0 = (c == 0 && ks == 0) ? 0u : 1u;
                mma_f16_ss(tmem, ah + 2 * ks, bh + 2 * ks, IDESC_BF16, en0);
                mma_f16_ss(tmem, ah + 2 * ks, bl + 2 * ks, IDESC_BF16, 1u);
                mma_f16_ss(tmem, al + 2 * ks, bh + 2 * ks, IDESC_BF16, 1u);
            }
            TC_COMMIT(sb + 16);
        }
    }

    MBAR_WAITP(sb + 16, 1u);
    asm volatile("tcgen05.fence::after_thread_sync;" ::: "memory");

    if (w < 4) {
        #pragma unroll
        for (int base = 0; base < 128; base += 32) {
            uint32_t dr[32];
            LDTM32(dr, tmem + base);
            TC_WAITLD();
            float* op = g_sim + (size_t)(row0 + w * 32 + lane) * CDIM + base;
            #pragma unroll
            for (int j = 0; j < 32; j += 4) {
                float4 o;
                o.x = __uint_as_float(dr[j + 0]) + sbias[base + j + 0];
                o.y = __uint_as_float(dr[j + 1]) + sbias[base + j + 1];
                o.z = __uint_as_float(dr[j + 2]) + sbias[base + j + 2];
                o.w = __uint_as_float(dr[j + 3]) + sbias[base + j + 3];
                *(float4*)(op + j) = o;
            }
        }
        asm volatile("tcgen05.fence::before_thread_sync;" ::: "memory");
    }
    __syncthreads();
    if (w == 0) {
        asm volatile("tcgen05.dealloc.cta_group::1.sync.aligned.b32 %0, %1;"
                     :: "r"(tmem), "r"(128u));
    }
#else
    // Generic-arch fallback (never executed on sm_103a; keeps compute_103 PTX legal).
    extern __shared__ __align__(1024) char smem[];
    float (*As)[128] = (float(*)[128])smem;
    float (*Bs)[128] = (float(*)[128])(smem + 8192);
    int tid = threadIdx.x;
    int row0 = blockIdx.x << 7;
    int ty = tid >> 4, tx = tid & 15;
    float acc[8][8] = {};
    const float* Hb = H + (size_t)row0 * KDIM;
    for (int kt = 0; kt < KDIM; kt += 16) {
        #pragma unroll
        for (int i = 0; i < 2; i++) {
            int id = tid + i * 256;
            int m = id >> 2, kk = (id & 3) << 2;
            float4 v = *(const float4*)(Hb + (size_t)m * KDIM + kt + kk);
            As[kk + 0][m] = v.x; As[kk + 1][m] = v.y;
            As[kk + 2][m] = v.z; As[kk + 3][m] = v.w;
        }
        #pragma unroll
        for (int i = 0; i < 2; i++) {
            int id = tid + i * 256;
            int k = id >> 5, n4 = (id & 31) << 2;
            *(float4*)&Bs[k][n4] = *(const float4*)(g_A + (kt + k) * CDIM + n4);
        }
        __syncthreads();
        #pragma unroll
        for (int k = 0; k < 16; k++) {
            float a[8], b[8];
            #pragma unroll
            for (int i = 0; i < 8; i++) a[i] = As[k][ty * 8 + i];
            #pragma unroll
            for (int j = 0; j < 8; j++) b[j] = Bs[k][tx * 8 + j];
            #pragma unroll
            for (int i = 0; i < 8; i++)
                #pragma unroll
                for (int j = 0; j < 8; j++) acc[i][j] += a[i] * b[j];
        }
        __syncthreads();
    }
    #pragma unroll
    for (int i = 0; i < 8; i++) {
        size_t r = row0 + ty * 8 + i;
        float* op = g_sim + r * CDIM + tx * 8;
        #pragma unroll
        for (int j = 0; j < 8; j++) op[j] = acc[i][j] + g_bias[tx * 8 + j];
    }
#endif
}

// ================= K2: softmax + context + per-node projection (float2 LDS) =================
__global__ __launch_bounds__(256) void k2_epi(float* __restrict__ out) {
    __shared__ float  snw[64 * 64];     // [f][h], row-major
    __shared__ float2 sLG[64 * 32];     // [m][p] -> {Lm, Gm}
    __shared__ float  sattn[8][128];
    __shared__ float  sfused[8][64];

    int n = blockIdx.x, tid = threadIdx.x;
    int w = tid >> 5, lane = tid & 31;

    {
        const float4* src = (const float4*)(g_nw + (size_t)n * 4096);
        float4* dst = (float4*)snw;
        #pragma unroll
        for (int i = 0; i < 4; i++) dst[tid + i * 256] = src[tid + i * 256];
        for (int i = tid; i < 2048; i += 256) sLG[i] = make_float2(g_Lm[i], g_Gm[i]);
    }
    __syncthreads();

    const float2* snw2 = (const float2*)snw;   // snw2[f*32 + h2] = {nw[f][2h2], nw[f][2h2+1]}

    for (int i = 0; i < 8; i++) {
        int b = i * 8 + w;
        size_t row = (size_t)b * N_NODES + n;
        const float* sp = g_sim + row * CDIM;
        float v0 = sp[lane], v1 = sp[lane + 32];
        float v2 = sp[lane + 64], v3 = sp[lane + 96];

        float mx = fmaxf(v0, v1);
        #pragma unroll
        for (int o = 16; o; o >>= 1) mx = fmaxf(mx, __shfl_xor_sync(0xffffffffu, mx, o));
        float e0 = __expf(v0 - mx), e1 = __expf(v1 - mx);
        float s = e0 + e1;
        #pragma unroll
        for (int o = 16; o; o >>= 1) s += __shfl_xor_sync(0xffffffffu, s, o);
        float inv = 1.f / s;
        sattn[w][lane] = e0 * inv; sattn[w][lane + 32] = e1 * inv;

        mx = fmaxf(v2, v3);
        #pragma unroll
        for (int o = 16; o; o >>= 1) mx = fmaxf(mx, __shfl_xor_sync(0xffffffffu, mx, o));
        float e2 = __expf(v2 - mx), e3 = __expf(v3 - mx);
        s = e2 + e3;
        #pragma unroll
        for (int o = 16; o; o >>= 1) s += __shfl_xor_sync(0xffffffffu, s, o);
        inv = 1.f / s;
        sattn[w][64 + lane] = e2 * inv; sattn[w][96 + lane] = e3 * inv;
        __syncwarp();

        // ctx: lane owns pattern p = lane; 1 LDS.64 per m
        float lctx = 0.f, gctx = 0.f;
        #pragma unroll 8
        for (int m = 0; m < 64; m++) {
            float2 lg = sLG[m * 32 + lane];
            lctx += sattn[w][m]      * lg.x;
            gctx += sattn[w][64 + m] * lg.y;
        }
        sfused[w][lane] = lctx; sfused[w][lane + 32] = gctx;
        __syncwarp();

        // out: lane owns h pair (2*lane, 2*lane+1); 1 LDS.64 per f
        float2 acc = make_float2(0.f, 0.f);
        #pragma unroll 8
        for (int f = 0; f < 64; f++) {
            float fv = sfused[w][f];
            float2 wv = snw2[f * 32 + lane];
            acc.x += fv * wv.x;
            acc.y += fv * wv.y;
        }
        *(float2*)(out + row * HID + 2 * lane) = acc;
        __syncwarp();
    }
}

// ================= launch =================
extern "C" void kernel_launch(void* const* d_in, const int* in_sizes, int n_in,
                              void* d_out, int out_size) {
    const float* H    = (const float*)d_in[0];   // [64,1024,12,64]
    const float* G    = (const float*)d_in[1];   // [64,6,32]
    const float* L    = (const float*)d_in[2];   // [64,12,32]
    const float* Wq   = (const float*)d_in[3];   // [64,32]
    const float* bq   = (const float*)d_in[4];   // [32]
    const float* emb  = (const float*)d_in[5];   // [1024,16]
    const float* pool = (const float*)d_in[6];   // [16,64,64]
    float* out = (float*)d_out;                  // [64,1024,64]

    static bool attr_done = false;
    if (!attr_done) {
        cudaFuncSetAttribute(k1_tc, cudaFuncAttributeMaxDynamicSharedMemorySize, K1_SMEM);
        attr_done = true;
    }

    // k2 now sits in captured launch slot 3.
    pFold_kernel<<<13, 256>>>(G, L, Wq, bq);       // slot 0
    pNw_kernel  <<<256, 256>>>(emb, pool);         // slot 1
    k1_tc       <<<ROWS / 128, 256, K1_SMEM>>>(H); // slot 2
    k2_epi      <<<N_NODES, 256>>>(out);           // slot 3  <-- profiled
}

// round 13
// speedup vs baseline: 1.3900x; 1.0929x over previous
#include <cuda_runtime.h>
#include <cuda_bf16.h>
#include <cstdint>

// ---------------- problem constants ----------------
#define B_BATCH 64
#define N_NODES 1024
#define S_LOC   12
#define HID     64
#define PAT     32
#define M_GLB   64
#define S_GLB   6
#define M_LOC   64
#define D_EMB   16
#define KDIM    768           // S_LOC * HID
#define CDIM    128           // M_LOC + M_GLB
#define ROWS    65536         // B_BATCH * N_NODES
#define NCHUNK  12            // K chunks of 64

// tcgen05 is arch-SPECIFIC: only emit its PTX in the sm_103a/sm_100a pass.
#if defined(__CUDA_ARCH_FEAT_SM103_ALL) || defined(__CUDA_ARCH_FEAT_SM100_ALL) || \
    (defined(__CUDA_ARCH_SPECIFIC__) && (__CUDA_ARCH_SPECIFIC__ == 1030 || __CUDA_ARCH_SPECIFIC__ == 1000))
#define HAS_TCGEN05 1
#else
#define HAS_TCGEN05 0
#endif

// ---------------- static device scratch ----------------
__device__ __align__(16) float g_A[KDIM * CDIM];           // only used by generic fallback
__device__ __align__(16) float g_bias[CDIM];
__device__ __align__(16) float g_Lm[M_LOC * PAT];
__device__ __align__(16) float g_Gm[M_GLB * PAT];
__device__ __align__(16) float g_nw[N_NODES * 64 * HID];   // [1024][64][64]
__device__ __align__(16) float g_sim[(size_t)ROWS * CDIM]; // logits [65536][128]
// pre-swizzled bf16 B operand (hi/lo), [chunk][128 n-rows][128 bytes]
__device__ __align__(16) unsigned char g_Bhi[NCHUNK * 128 * 128];
__device__ __align__(16) unsigned char g_Blo[NCHUNK * 128 * 128];

// ---------------- helpers legal on all targets ----------------
__device__ __forceinline__ uint32_t su32(const void* p) {
    uint32_t a;
    asm("{ .reg .u64 t; cvta.to.shared.u64 t, %1; cvt.u32.u64 %0, t; }" : "=r"(a) : "l"(p));
    return a;
}
__device__ __forceinline__ uint32_t bf16pack(float x0, float x1) {
    uint32_t r;
    asm("cvt.rn.bf16x2.f32 %0, %1, %2;" : "=r"(r) : "f"(x1), "f"(x0));
    return r;
}
__device__ __forceinline__ void bf16split(float x0, float x1, uint32_t& hi, uint32_t& lo) {
    hi = bf16pack(x0, x1);
    float h0 = __uint_as_float(hi << 16);
    float h1 = __uint_as_float(hi & 0xffff0000u);
    lo = bf16pack(x0 - h0, x1 - h1);
}
__device__ __forceinline__ void cp16(uint32_t saddr, const void* gaddr) {
    asm volatile("cp.async.cg.shared.global [%0], [%1], 16;" :: "r"(saddr), "l"(gaddr) : "memory");
}

#if HAS_TCGEN05
__device__ __forceinline__ uint32_t elect1() {
    uint32_t r;
    asm volatile("{ .reg .pred p; elect.sync _|p, 0xFFFFFFFF; selp.b32 %0, 1, 0, p; }" : "=r"(r));
    return r;
}
__device__ __forceinline__ uint64_t mkdesc(uint32_t saddr) {
    // SW128 K-major: layout=2, version=1, SBO=64, LBO=1
    return 0x4000404000010000ULL | ((uint64_t)(saddr >> 4) & 0x3FFF);
}
__device__ __forceinline__ void mma_f16_ss(uint32_t d, uint64_t ad, uint64_t bd,
                                           uint32_t idesc, uint32_t en) {
    asm volatile(
        "{\n\t.reg .pred p;\n\tsetp.ne.u32 p, %4, 0;\n\t"
        "tcgen05.mma.cta_group::1.kind::f16 [%0], %1, %2, %3, {%5, %5, %5, %5}, p;\n\t}"
        :: "r"(d), "l"(ad), "l"(bd), "r"(idesc), "r"(en), "r"(0u) : "memory");
}
#define MBAR_INIT(a, n) asm volatile("mbarrier.init.shared.b64 [%0], %1;" :: "r"(a), "r"(n) : "memory")
#define MBAR_WAITP(addr, par) do {                                                      \
    uint32_t _m = (addr), _p = (par), _d;                                               \
    asm volatile("{\n\t.reg .pred p;\n\t"                                               \
        "mbarrier.try_wait.parity.acquire.cta.shared::cta.b64 p, [%1], %2;\n\t"         \
        "selp.b32 %0, 1, 0, p;\n\t}" : "=r"(_d) : "r"(_m), "r"(_p) : "memory");         \
    if (!_d) {                                                                          \
        asm volatile("{\n\t.reg .pred P1;\n\tWL_%=:\n\t"                                \
            "mbarrier.try_wait.parity.acquire.cta.shared::cta.b64 P1, [%0], %1, 0x989680;\n\t" \
            "@P1 bra.uni WD_%=;\n\tbra.uni WL_%=;\n\tWD_%=:\n\t}"                       \
            :: "r"(_m), "r"(_p) : "memory");                                            \
    }                                                                                   \
} while (0)
#define TC_COMMIT(a) asm volatile("tcgen05.commit.cta_group::1.mbarrier::arrive::one.shared::cluster.b64 [%0];" :: "r"(a) : "memory")
#define TC_WAITLD()  asm volatile("tcgen05.wait::ld.sync.aligned;" ::: "memory")
#define LDTM32(r, a) asm volatile(                                                      \
    "tcgen05.ld.sync.aligned.32x32b.x32.b32 "                                           \
    "{%0, %1, %2, %3, %4, %5, %6, %7, %8, %9, %10, %11, %12, %13, %14, %15, "           \
    " %16, %17, %18, %19, %20, %21, %22, %23, %24, %25, %26, %27, %28, %29, %30, %31}, [%32];" \
    : "=r"((r)[0]), "=r"((r)[1]), "=r"((r)[2]), "=r"((r)[3]),                           \
      "=r"((r)[4]), "=r"((r)[5]), "=r"((r)[6]), "=r"((r)[7]),                           \
      "=r"((r)[8]), "=r"((r)[9]), "=r"((r)[10]), "=r"((r)[11]),                         \
      "=r"((r)[12]), "=r"((r)[13]), "=r"((r)[14]), "=r"((r)[15]),                       \
      "=r"((r)[16]), "=r"((r)[17]), "=r"((r)[18]), "=r"((r)[19]),                       \
      "=r"((r)[20]), "=r"((r)[21]), "=r"((r)[22]), "=r"((r)[23]),                       \
      "=r"((r)[24]), "=r"((r)[25]), "=r"((r)[26]), "=r"((r)[27]),                       \
      "=r"((r)[28]), "=r"((r)[29]), "=r"((r)[30]), "=r"((r)[31])                        \
    : "r"(a))
// idesc: fp32 accum, bf16 x bf16, M=128, N=128, K-major both
#define IDESC_BF16 0x8200490u
#endif  // HAS_TCGEN05

// ================= P0: pFold — folded-weight split/swizzle + bias + means =================
__global__ __launch_bounds__(256) void pFold_kernel(const float* __restrict__ G,
                                                    const float* __restrict__ L,
                                                    const float* __restrict__ Wq,
                                                    const float* __restrict__ bq) {
    int blk = blockIdx.x, tid = threadIdx.x;
    if (blk < 12) {
        __shared__ float sWq[64][36];
        __shared__ float sBl[64][36];
        __shared__ float sBg[64][36];
        int ci = blk;
        for (int i = tid; i < 64 * 32; i += 256) sWq[i >> 5][i & 31] = Wq[i];
        for (int i = tid; i < 2048; i += 256) {
            int c = i >> 5, p = i & 31;
            sBl[c][p] = L[c * (S_LOC * PAT) + ci * PAT + p];
            sBg[c][p] = G[c * (S_GLB * PAT) + (ci >> 1) * PAT + p];
        }
        __syncthreads();
        #pragma unroll
        for (int it = 0; it < 4; it++) {
            int task = it * 256 + tid;
            int kq = (task >> 7) & 7;
            int n  = task & 127;
            const float* bank = (n < 64) ? &sBl[n][0] : &sBg[n - 64][0];
            float scale = (n < 64) ? 1.0f : 0.5f;
            uint32_t hi[4], lo[4];
            #pragma unroll
            for (int p2 = 0; p2 < 4; p2++) {
                int h0 = kq * 8 + 2 * p2;
                float x0 = 0.f, x1 = 0.f;
                #pragma unroll
                for (int p = 0; p < 32; p++) {
                    float bp = bank[p];
                    x0 += sWq[h0][p] * bp;
                    x1 += sWq[h0 + 1][p] * bp;
                }
                bf16split(x0 * scale, x1 * scale, hi[p2], lo[p2]);
            }
            int off = n * 128 + kq * 16;
            int swo = off ^ ((off >> 3) & 0x70);
            *(uint4*)(g_Bhi + ci * 16384 + swo) = make_uint4(hi[0], hi[1], hi[2], hi[3]);
            *(uint4*)(g_Blo + ci * 16384 + swo) = make_uint4(lo[0], lo[1], lo[2], lo[3]);
        }
    } else {
        if (tid < 128) {
            int c = tid;
            float v = 0.f;
            if (c < 64) {
                for (int s = 0; s < S_LOC; s++)
                    #pragma unroll
                    for (int p = 0; p < PAT; p++) v += bq[p] * L[c * (S_LOC * PAT) + s * PAT + p];
            } else {
                for (int s = 0; s < S_GLB; s++)
                    #pragma unroll
                    for (int p = 0; p < PAT; p++) v += bq[p] * G[(c - 64) * (S_GLB * PAT) + s * PAT + p];
            }
            g_bias[c] = v;
        }
        for (int idx = tid; idx < 2048; idx += 256) {
            int m = idx >> 5, p = idx & 31;
            float lm = 0.f, gm = 0.f;
            for (int s = 0; s < S_LOC; s++) lm += L[m * (S_LOC * PAT) + s * PAT + p];
            for (int s = 0; s < S_GLB; s++) gm += G[m * (S_GLB * PAT) + s * PAT + p];
            g_Lm[idx] = lm * (1.f / 12.f);
            g_Gm[idx] = gm * (1.f / 6.f);
        }
    }
}

// ================= P1: node_w = emb @ pool (4 nodes/block, float4 ILP) =================
__global__ __launch_bounds__(256) void pNw_kernel(const float* __restrict__ emb,
                                                  const float* __restrict__ pool) {
    __shared__ float se[4][16];
    int n0 = blockIdx.x << 2, tid = threadIdx.x;
    if (tid < 64) se[tid >> 4][tid & 15] = emb[(n0 + (tid >> 4)) * D_EMB + (tid & 15)];
    __syncthreads();
    float e0[16], e1[16], e2[16], e3[16];
    #pragma unroll
    for (int d = 0; d < 16; d++) {
        e0[d] = se[0][d]; e1[d] = se[1][d]; e2[d] = se[2][d]; e3[d] = se[3][d];
    }
    const float4* p4 = (const float4*)pool;
    #pragma unroll
    for (int j = 0; j < 4; j++) {
        int o = j * 256 + tid;
        float4 a0 = {0, 0, 0, 0}, a1 = a0, a2 = a0, a3 = a0;
        #pragma unroll
        for (int d = 0; d < 16; d++) {
            float4 pv = p4[d * 1024 + o];
            a0.x += e0[d] * pv.x; a0.y += e0[d] * pv.y; a0.z += e0[d] * pv.z; a0.w += e0[d] * pv.w;
            a1.x += e1[d] * pv.x; a1.y += e1[d] * pv.y; a1.z += e1[d] * pv.z; a1.w += e1[d] * pv.w;
            a2.x += e2[d] * pv.x; a2.y += e2[d] * pv.y; a2.z += e2[d] * pv.z; a2.w += e2[d] * pv.w;
            a3.x += e3[d] * pv.x; a3.y += e3[d] * pv.y; a3.z += e3[d] * pv.z; a3.w += e3[d] * pv.w;
        }
        float4* nw4 = (float4*)g_nw;
        nw4[(size_t)(n0 + 0) * 1024 + o] = a0;
        nw4[(size_t)(n0 + 1) * 1024 + o] = a1;
        nw4[(size_t)(n0 + 2) * 1024 + o] = a2;
        nw4[(size_t)(n0 + 3) * 1024 + o] = a3;
    }
}

// ================= K1: tcgen05 bf16x3 GEMM (R10-proven, unchanged) =================
#define K1_SMEM (1024 + 65536)
__global__ __launch_bounds__(256) void k1_tc(const float* __restrict__ H) {
#if HAS_TCGEN05
    extern __shared__ __align__(1024) char smem[];
    const int tid = threadIdx.x, w = tid >> 5, lane = tid & 31;
    const int row0 = blockIdx.x << 7;
    uint32_t sb = su32(smem);

    if (w == 0) {
        asm volatile("tcgen05.alloc.cta_group::1.sync.aligned.shared::cta.b32 [%0], %1;"
                     :: "r"(sb), "r"(128u) : "memory");
        asm volatile("tcgen05.relinquish_alloc_permit.cta_group::1.sync.aligned;");
    }
    if (tid == 0) MBAR_INIT(sb + 16, 1);
    float* sbias = (float*)(smem + 64);
    if (tid < 128) sbias[tid] = g_bias[tid];
    __syncthreads();
    uint32_t tmem;
    asm("ld.shared.b32 %0, [%1];" : "=r"(tmem) : "r"(sb));

    char* buf = smem + 1024;
    const uint32_t bufb = sb + 1024;

    for (int c = 0; c < NCHUNK; c++) {
        if (c > 0) MBAR_WAITP(sb + 16, (uint32_t)((c - 1) & 1));

        {
            const char* bh = (const char*)g_Bhi + c * 16384 + tid * 16;
            const char* bl = (const char*)g_Blo + c * 16384 + tid * 16;
            uint32_t dh = bufb + 32768 + tid * 16;
            uint32_t dl = bufb + 49152 + tid * 16;
            #pragma unroll
            for (int i = 0; i < 4; i++) {
                cp16(dh + i * 4096, bh + i * 4096);
                cp16(dl + i * 4096, bl + i * 4096);
            }
            asm volatile("cp.async.commit_group;" ::: "memory");
        }
        #pragma unroll
        for (int it = 0; it < 4; it++) {
            int task = it * 256 + tid;
            int r = task >> 3, kq = task & 7;
            const float* hp = H + (size_t)(row0 + r) * KDIM + c * 64 + kq * 8;
            float4 u0 = *(const float4*)hp;
            float4 u1 = *(const float4*)(hp + 4);
            uint32_t hi[4], lo[4];
            bf16split(u0.x, u0.y, hi[0], lo[0]);
            bf16split(u0.z, u0.w, hi[1], lo[1]);
            bf16split(u1.x, u1.y, hi[2], lo[2]);
            bf16split(u1.z, u1.w, hi[3], lo[3]);
            int off = r * 128 + kq * 16;
            int swo = off ^ ((off >> 3) & 0x70);
            *(uint4*)(buf + swo)         = make_uint4(hi[0], hi[1], hi[2], hi[3]);
            *(uint4*)(buf + 16384 + swo) = make_uint4(lo[0], lo[1], lo[2], lo[3]);
        }
        asm volatile("cp.async.wait_group 0;" ::: "memory");
        asm volatile("fence.proxy.async.shared::cta;" ::: "memory");
        __syncthreads();

        if (w == 0 && elect1()) {
            uint64_t ah = mkdesc(bufb);
            uint64_t al = mkdesc(bufb + 16384);
            uint64_t bh = mkdesc(bufb + 32768);
            uint64_t bl = mkdesc(bufb + 49152);
            #pragma unroll
            for (int ks = 0; ks < 4; ks++) {
                uint32_t en0 = (c == 0 && ks == 0) ? 0u : 1u;
                mma_f16_ss(tmem, ah + 2 * ks, bh + 2 * ks, IDESC_BF16, en0);
                mma_f16_ss(tmem, ah + 2 * ks, bl + 2 * ks, IDESC_BF16, 1u);
                mma_f16_ss(tmem, al + 2 * ks, bh + 2 * ks, IDESC_BF16, 1u);
            }
            TC_COMMIT(sb + 16);
        }
    }

    MBAR_WAITP(sb + 16, 1u);
    asm volatile("tcgen05.fence::after_thread_sync;" ::: "memory");

    if (w < 4) {
        #pragma unroll
        for (int base = 0; base < 128; base += 32) {
            uint32_t dr[32];
            LDTM32(dr, tmem + base);
            TC_WAITLD();
            float* op = g_sim + (size_t)(row0 + w * 32 + lane) * CDIM + base;
            #pragma unroll
            for (int j = 0; j < 32; j += 4) {
                float4 o;
                o.x = __uint_as_float(dr[j + 0]) + sbias[base + j + 0];
                o.y = __uint_as_float(dr[j + 1]) + sbias[base + j + 1];
                o.z = __uint_as_float(dr[j + 2]) + sbias[base + j + 2];
                o.w = __uint_as_float(dr[j + 3]) + sbias[base + j + 3];
                *(float4*)(op + j) = o;
            }
        }
        asm volatile("tcgen05.fence::before_thread_sync;" ::: "memory");
    }
    __syncthreads();
    if (w == 0) {
        asm volatile("tcgen05.dealloc.cta_group::1.sync.aligned.b32 %0, %1;"
                     :: "r"(tmem), "r"(128u));
    }
#else
    // Generic-arch fallback (never executed on sm_103a; keeps compute_103 PTX legal).
    extern __shared__ __align__(1024) char smem[];
    float (*As)[128] = (float(*)[128])smem;
    float (*Bs)[128] = (float(*)[128])(smem + 8192);
    int tid = threadIdx.x;
    int row0 = blockIdx.x << 7;
    int ty = tid >> 4, tx = tid & 15;
    float acc[8][8] = {};
    const float* Hb = H + (size_t)row0 * KDIM;
    for (int kt = 0; kt < KDIM; kt += 16) {
        #pragma unroll
        for (int i = 0; i < 2; i++) {
            int id = tid + i * 256;
            int m = id >> 2, kk = (id & 3) << 2;
            float4 v = *(const float4*)(Hb + (size_t)m * KDIM + kt + kk);
            As[kk + 0][m] = v.x; As[kk + 1][m] = v.y;
            As[kk + 2][m] = v.z; As[kk + 3][m] = v.w;
        }
        #pragma unroll
        for (int i = 0; i < 2; i++) {
            int id = tid + i * 256;
            int k = id >> 5, n4 = (id & 31) << 2;
            *(float4*)&Bs[k][n4] = *(const float4*)(g_A + (kt + k) * CDIM + n4);
        }
        __syncthreads();
        #pragma unroll
        for (int k = 0; k < 16; k++) {
            float a[8], b[8];
            #pragma unroll
            for (int i = 0; i < 8; i++) a[i] = As[k][ty * 8 + i];
            #pragma unroll
            for (int j = 0; j < 8; j++) b[j] = Bs[k][tx * 8 + j];
            #pragma unroll
            for (int i = 0; i < 8; i++)
                #pragma unroll
                for (int j = 0; j < 8; j++) acc[i][j] += a[i] * b[j];
        }
        __syncthreads();
    }
    #pragma unroll
    for (int i = 0; i < 8; i++) {
        size_t r = row0 + ty * 8 + i;
        float* op = g_sim + r * CDIM + tx * 8;
        #pragma unroll
        for (int j = 0; j < 8; j++) op[j] = acc[i][j] + g_bias[tx * 8 + j];
    }
#endif
}

// ================= K2: register-blocked softmax + ctx + projection =================
// Dynamic smem layout (bytes):
//   [0..16384)        snw  [64*64] float        (node weights, float2-read)
//   [16384..32768)    sLG  [64*32] float2       ({Lm,Gm})
//   [32768..81920)    satt [8 warps][128 m][12] (attn transposed; rows 48B, float4-aligned)
//   [81920..106496)   sfus [8 warps][64 f][12]  (fused transposed)
#define K2_SMEM 106496
__global__ __launch_bounds__(256) void k2_epi(float* __restrict__ out) {
    extern __shared__ __align__(16) char sm2[];
    float*  snw  = (float*)sm2;
    float2* sLG  = (float2*)(sm2 + 16384);
    int n = blockIdx.x, tid = threadIdx.x;
    int w = tid >> 5, lane = tid & 31;
    float* satt = (float*)(sm2 + 32768) + w * (128 * 12);
    float* sfus = (float*)(sm2 + 81920) + w * (64 * 12);

    {
        const float4* src = (const float4*)(g_nw + (size_t)n * 4096);
        float4* dst = (float4*)snw;
        #pragma unroll
        for (int i = 0; i < 4; i++) dst[tid + i * 256] = src[tid + i * 256];
        for (int i = tid; i < 2048; i += 256) sLG[i] = make_float2(g_Lm[i], g_Gm[i]);
    }
    __syncthreads();

    // ---- phase 1: softmax for this warp's 8 rows (b = i*8 + w), attn -> satt[m][i] ----
    for (int i = 0; i < 8; i++) {
        int b = i * 8 + w;
        size_t row = (size_t)b * N_NODES + n;
        const float* sp = g_sim + row * CDIM;
        float v0 = sp[lane], v1 = sp[lane + 32];
        float v2 = sp[lane + 64], v3 = sp[lane + 96];

        float mx = fmaxf(v0, v1);
        #pragma unroll
        for (int o = 16; o; o >>= 1) mx = fmaxf(mx, __shfl_xor_sync(0xffffffffu, mx, o));
        float e0 = __expf(v0 - mx), e1 = __expf(v1 - mx);
        float s = e0 + e1;
        #pragma unroll
        for (int o = 16; o; o >>= 1) s += __shfl_xor_sync(0xffffffffu, s, o);
        float inv = 1.f / s;

        float mx2 = fmaxf(v2, v3);
        #pragma unroll
        for (int o = 16; o; o >>= 1) mx2 = fmaxf(mx2, __shfl_xor_sync(0xffffffffu, mx2, o));
        float e2 = __expf(v2 - mx2), e3 = __expf(v3 - mx2);
        float s2 = e2 + e3;
        #pragma unroll
        for (int o = 16; o; o >>= 1) s2 += __shfl_xor_sync(0xffffffffu, s2, o);
        float inv2 = 1.f / s2;

        satt[(lane)      * 12 + i] = e0 * inv;
        satt[(lane + 32) * 12 + i] = e1 * inv;
        satt[(lane + 64) * 12 + i] = e2 * inv2;
        satt[(lane + 96) * 12 + i] = e3 * inv2;
    }
    __syncwarp();

    // ---- phase 2: ctx, register-blocked over 8 rows; lane owns pattern p = lane ----
    float lctx[8] = {0, 0, 0, 0, 0, 0, 0, 0};
    float gctx[8] = {0, 0, 0, 0, 0, 0, 0, 0};
    #pragma unroll 4
    for (int m = 0; m < 64; m++) {
        float2 lg = sLG[m * 32 + lane];
        float4 al0 = *(const float4*)&satt[m * 12];
        float4 al1 = *(const float4*)&satt[m * 12 + 4];
        float4 ag0 = *(const float4*)&satt[(m + 64) * 12];
        float4 ag1 = *(const float4*)&satt[(m + 64) * 12 + 4];
        lctx[0] += al0.x * lg.x; lctx[1] += al0.y * lg.x;
        lctx[2] += al0.z * lg.x; lctx[3] += al0.w * lg.x;
        lctx[4] += al1.x * lg.x; lctx[5] += al1.y * lg.x;
        lctx[6] += al1.z * lg.x; lctx[7] += al1.w * lg.x;
        gctx[0] += ag0.x * lg.y; gctx[1] += ag0.y * lg.y;
        gctx[2] += ag0.z * lg.y; gctx[3] += ag0.w * lg.y;
        gctx[4] += ag1.x * lg.y; gctx[5] += ag1.y * lg.y;
        gctx[6] += ag1.z * lg.y; gctx[7] += ag1.w * lg.y;
    }
    // fused -> sfus[f][r]: lane f = lane (local half), lane+32 (global half)
    #pragma unroll
    for (int r = 0; r < 8; r++) {
        sfus[lane * 12 + r]        = lctx[r];
        sfus[(lane + 32) * 12 + r] = gctx[r];
    }
    __syncwarp();

    // ---- phase 3: out, register-blocked; lane owns h pair (2*lane, 2*lane+1) ----
    const float2* snw2 = (const float2*)snw;
    float2 acc[8];
    #pragma unroll
    for (int r = 0; r < 8; r++) acc[r] = make_float2(0.f, 0.f);
    #pragma unroll 4
    for (int f = 0; f < 64; f++) {
        float2 wv = snw2[f * 32 + lane];
        float4 fr0 = *(const float4*)&sfus[f * 12];
        float4 fr1 = *(const float4*)&sfus[f * 12 + 4];
        acc[0].x += fr0.x * wv.x; acc[0].y += fr0.x * wv.y;
        acc[1].x += fr0.y * wv.x; acc[1].y += fr0.y * wv.y;
        acc[2].x += fr0.z * wv.x; acc[2].y += fr0.z * wv.y;
        acc[3].x += fr0.w * wv.x; acc[3].y += fr0.w * wv.y;
        acc[4].x += fr1.x * wv.x; acc[4].y += fr1.x * wv.y;
        acc[5].x += fr1.y * wv.x; acc[5].y += fr1.y * wv.y;
        acc[6].x += fr1.z * wv.x; acc[6].y += fr1.z * wv.y;
        acc[7].x += fr1.w * wv.x; acc[7].y += fr1.w * wv.y;
    }
    #pragma unroll
    for (int r = 0; r < 8; r++) {
        size_t row = (size_t)(r * 8 + w) * N_NODES + n;
        *(float2*)(out + row * HID + 2 * lane) = acc[r];
    }
}

// ================= launch =================
extern "C" void kernel_launch(void* const* d_in, const int* in_sizes, int n_in,
                              void* d_out, int out_size) {
    const float* H    = (const float*)d_in[0];   // [64,1024,12,64]
    const float* G    = (const float*)d_in[1];   // [64,6,32]
    const float* L    = (const float*)d_in[2];   // [64,12,32]
    const float* Wq   = (const float*)d_in[3];   // [64,32]
    const float* bq   = (const float*)d_in[4];   // [32]
    const float* emb  = (const float*)d_in[5];   // [1024,16]
    const float* pool = (const float*)d_in[6];   // [16,64,64]
    float* out = (float*)d_out;                  // [64,1024,64]

    static bool attr_done = false;
    if (!attr_done) {
        cudaFuncSetAttribute(k1_tc, cudaFuncAttributeMaxDynamicSharedMemorySize, K1_SMEM);
        cudaFuncSetAttribute(k2_epi, cudaFuncAttributeMaxDynamicSharedMemorySize, K2_SMEM);
        attr_done = true;
    }

    // k2 stays in captured launch slot 3.
    pFold_kernel<<<13, 256>>>(G, L, Wq, bq);             // slot 0
    pNw_kernel  <<<256, 256>>>(emb, pool);               // slot 1
    k1_tc       <<<ROWS / 128, 256, K1_SMEM>>>(H);       // slot 2
    k2_epi      <<<N_NODES, 256, K2_SMEM>>>(out);        // slot 3  <-- profiled
}

// round 16
// speedup vs baseline: 1.5328x; 1.1028x over previous
#include <cuda_runtime.h>
#include <cuda_bf16.h>
#include <cstdint>

// ---------------- problem constants ----------------
#define B_BATCH 64
#define N_NODES 1024
#define S_LOC   12
#define HID     64
#define PAT     32
#define M_GLB   64
#define S_GLB   6
#define M_LOC   64
#define D_EMB   16
#define KDIM    768           // S_LOC * HID
#define CDIM    128           // M_LOC + M_GLB
#define ROWS    65536         // B_BATCH * N_NODES
#define NCHUNK  12            // K chunks of 64

// tcgen05 is arch-SPECIFIC: only emit its PTX in the sm_103a/sm_100a pass.
#if defined(__CUDA_ARCH_FEAT_SM103_ALL) || defined(__CUDA_ARCH_FEAT_SM100_ALL) || \
    (defined(__CUDA_ARCH_SPECIFIC__) && (__CUDA_ARCH_SPECIFIC__ == 1030 || __CUDA_ARCH_SPECIFIC__ == 1000))
#define HAS_TCGEN05 1
#else
#define HAS_TCGEN05 0
#endif

// ---------------- static device scratch ----------------
__device__ __align__(16) float g_A[KDIM * CDIM];           // only used by generic fallback
__device__ __align__(16) float g_bias[CDIM];
__device__ __align__(16) float g_Lm[M_LOC * PAT];
__device__ __align__(16) float g_Gm[M_GLB * PAT];
__device__ __align__(16) float g_nw[N_NODES * 64 * HID];   // [1024][64][64]
__device__ __align__(16) float g_sim[(size_t)ROWS * CDIM]; // logits [65536][128]
// pre-swizzled bf16 B operand (hi/lo), [chunk][128 n-rows][128 bytes]
__device__ __align__(16) unsigned char g_Bhi[NCHUNK * 128 * 128];
__device__ __align__(16) unsigned char g_Blo[NCHUNK * 128 * 128];

// ---------------- helpers legal on all targets ----------------
__device__ __forceinline__ uint32_t su32(const void* p) {
    uint32_t a;
    asm("{ .reg .u64 t; cvta.to.shared.u64 t, %1; cvt.u32.u64 %0, t; }" : "=r"(a) : "l"(p));
    return a;
}
__device__ __forceinline__ uint32_t bf16pack(float x0, float x1) {
    uint32_t r;
    asm("cvt.rn.bf16x2.f32 %0, %1, %2;" : "=r"(r) : "f"(x1), "f"(x0));
    return r;
}
__device__ __forceinline__ void bf16split(float x0, float x1, uint32_t& hi, uint32_t& lo) {
    hi = bf16pack(x0, x1);
    float h0 = __uint_as_float(hi << 16);
    float h1 = __uint_as_float(hi & 0xffff0000u);
    lo = bf16pack(x0 - h0, x1 - h1);
}
__device__ __forceinline__ void cp16(uint32_t saddr, const void* gaddr) {
    asm volatile("cp.async.cg.shared.global [%0], [%1], 16;" :: "r"(saddr), "l"(gaddr) : "memory");
}

#if HAS_TCGEN05
__device__ __forceinline__ uint32_t elect1() {
    uint32_t r;
    asm volatile("{ .reg .pred p; elect.sync _|p, 0xFFFFFFFF; selp.b32 %0, 1, 0, p; }" : "=r"(r));
    return r;
}
__device__ __forceinline__ uint64_t mkdesc(uint32_t saddr) {
    // SW128 K-major: layout=2, version=1, SBO=64, LBO=1
    return 0x4000404000010000ULL | ((uint64_t)(saddr >> 4) & 0x3FFF);
}
__device__ __forceinline__ void mma_f16_ss(uint32_t d, uint64_t ad, uint64_t bd,
                                           uint32_t idesc, uint32_t en) {
    asm volatile(
        "{\n\t.reg .pred p;\n\tsetp.ne.u32 p, %4, 0;\n\t"
        "tcgen05.mma.cta_group::1.kind::f16 [%0], %1, %2, %3, {%5, %5, %5, %5}, p;\n\t}"
        :: "r"(d), "l"(ad), "l"(bd), "r"(idesc), "r"(en), "r"(0u) : "memory");
}
#define MBAR_INIT(a, n) asm volatile("mbarrier.init.shared.b64 [%0], %1;" :: "r"(a), "r"(n) : "memory")
#define MBAR_WAITP(addr, par) do {                                                      \
    uint32_t _m = (addr), _p = (par), _d;                                               \
    asm volatile("{\n\t.reg .pred p;\n\t"                                               \
        "mbarrier.try_wait.parity.acquire.cta.shared::cta.b64 p, [%1], %2;\n\t"         \
        "selp.b32 %0, 1, 0, p;\n\t}" : "=r"(_d) : "r"(_m), "r"(_p) : "memory");         \
    if (!_d) {                                                                          \
        asm volatile("{\n\t.reg .pred P1;\n\tWL_%=:\n\t"                                \
            "mbarrier.try_wait.parity.acquire.cta.shared::cta.b64 P1, [%0], %1, 0x989680;\n\t" \
            "@P1 bra.uni WD_%=;\n\tbra.uni WL_%=;\n\tWD_%=:\n\t}"                       \
            :: "r"(_m), "r"(_p) : "memory");                                            \
    }                                                                                   \
} while (0)
#define TC_COMMIT(a) asm volatile("tcgen05.commit.cta_group::1.mbarrier::arrive::one.shared::cluster.b64 [%0];" :: "r"(a) : "memory")
#define TC_WAITLD()  asm volatile("tcgen05.wait::ld.sync.aligned;" ::: "memory")
#define LDTM32(r, a) asm volatile(                                                      \
    "tcgen05.ld.sync.aligned.32x32b.x32.b32 "                                           \
    "{%0, %1, %2, %3, %4, %5, %6, %7, %8, %9, %10, %11, %12, %13, %14, %15, "           \
    " %16, %17, %18, %19, %20, %21, %22, %23, %24, %25, %26, %27, %28, %29, %30, %31}, [%32];" \
    : "=r"((r)[0]), "=r"((r)[1]), "=r"((r)[2]), "=r"((r)[3]),                           \
      "=r"((r)[4]), "=r"((r)[5]), "=r"((r)[6]), "=r"((r)[7]),                           \
      "=r"((r)[8]), "=r"((r)[9]), "=r"((r)[10]), "=r"((r)[11]),                         \
      "=r"((r)[12]), "=r"((r)[13]), "=r"((r)[14]), "=r"((r)[15]),                       \
      "=r"((r)[16]), "=r"((r)[17]), "=r"((r)[18]), "=r"((r)[19]),                       \
      "=r"((r)[20]), "=r"((r)[21]), "=r"((r)[22]), "=r"((r)[23]),                       \
      "=r"((r)[24]), "=r"((r)[25]), "=r"((r)[26]), "=r"((r)[27]),                       \
      "=r"((r)[28]), "=r"((r)[29]), "=r"((r)[30]), "=r"((r)[31])                        \
    : "r"(a))
// idesc: fp32 accum, bf16 x bf16, M=128, N=128, K-major both
#define IDESC_BF16 0x8200490u
#endif  // HAS_TCGEN05

// ================= P0: pFold — folded-weight split/swizzle + bias + means =================
__global__ __launch_bounds__(256) void pFold_kernel(const float* __restrict__ G,
                                                    const float* __restrict__ L,
                                                    const float* __restrict__ Wq,
                                                    const float* __restrict__ bq) {
    int blk = blockIdx.x, tid = threadIdx.x;
    if (blk < 12) {
        __shared__ float sWq[64][36];
        __shared__ float sBl[64][36];
        __shared__ float sBg[64][36];
        int ci = blk;
        for (int i = tid; i < 64 * 32; i += 256) sWq[i >> 5][i & 31] = Wq[i];
        for (int i = tid; i < 2048; i += 256) {
            int c = i >> 5, p = i & 31;
            sBl[c][p] = L[c * (S_LOC * PAT) + ci * PAT + p];
            sBg[c][p] = G[c * (S_GLB * PAT) + (ci >> 1) * PAT + p];
        }
        __syncthreads();
        #pragma unroll
        for (int it = 0; it < 4; it++) {
            int task = it * 256 + tid;
            int kq = (task >> 7) & 7;
            int n  = task & 127;
            const float* bank = (n < 64) ? &sBl[n][0] : &sBg[n - 64][0];
            float scale = (n < 64) ? 1.0f : 0.5f;
            uint32_t hi[4], lo[4];
            #pragma unroll
            for (int p2 = 0; p2 < 4; p2++) {
                int h0 = kq * 8 + 2 * p2;
                float x0 = 0.f, x1 = 0.f;
                #pragma unroll
                for (int p = 0; p < 32; p++) {
                    float bp = bank[p];
                    x0 += sWq[h0][p] * bp;
                    x1 += sWq[h0 + 1][p] * bp;
                }
                bf16split(x0 * scale, x1 * scale, hi[p2], lo[p2]);
            }
            int off = n * 128 + kq * 16;
            int swo = off ^ ((off >> 3) & 0x70);
            *(uint4*)(g_Bhi + ci * 16384 + swo) = make_uint4(hi[0], hi[1], hi[2], hi[3]);
            *(uint4*)(g_Blo + ci * 16384 + swo) = make_uint4(lo[0], lo[1], lo[2], lo[3]);
        }
    } else {
        if (tid < 128) {
            int c = tid;
            float v = 0.f;
            if (c < 64) {
                for (int s = 0; s < S_LOC; s++)
                    #pragma unroll
                    for (int p = 0; p < PAT; p++) v += bq[p] * L[c * (S_LOC * PAT) + s * PAT + p];
            } else {
                for (int s = 0; s < S_GLB; s++)
                    #pragma unroll
                    for (int p = 0; p < PAT; p++) v += bq[p] * G[(c - 64) * (S_GLB * PAT) + s * PAT + p];
            }
            g_bias[c] = v;
        }
        for (int idx = tid; idx < 2048; idx += 256) {
            int m = idx >> 5, p = idx & 31;
            float lm = 0.f, gm = 0.f;
            for (int s = 0; s < S_LOC; s++) lm += L[m * (S_LOC * PAT) + s * PAT + p];
            for (int s = 0; s < S_GLB; s++) gm += G[m * (S_GLB * PAT) + s * PAT + p];
            g_Lm[idx] = lm * (1.f / 12.f);
            g_Gm[idx] = gm * (1.f / 6.f);
        }
    }
}

// ================= P1: node_w = emb @ pool (4 nodes/block, float4 ILP) =================
__global__ __launch_bounds__(256) void pNw_kernel(const float* __restrict__ emb,
                                                  const float* __restrict__ pool) {
    __shared__ float se[4][16];
    int n0 = blockIdx.x << 2, tid = threadIdx.x;
    if (tid < 64) se[tid >> 4][tid & 15] = emb[(n0 + (tid >> 4)) * D_EMB + (tid & 15)];
    __syncthreads();
    float e0[16], e1[16], e2[16], e3[16];
    #pragma unroll
    for (int d = 0; d < 16; d++) {
        e0[d] = se[0][d]; e1[d] = se[1][d]; e2[d] = se[2][d]; e3[d] = se[3][d];
    }
    const float4* p4 = (const float4*)pool;
    #pragma unroll
    for (int j = 0; j < 4; j++) {
        int o = j * 256 + tid;
        float4 a0 = {0, 0, 0, 0}, a1 = a0, a2 = a0, a3 = a0;
        #pragma unroll
        for (int d = 0; d < 16; d++) {
            float4 pv = p4[d * 1024 + o];
            a0.x += e0[d] * pv.x; a0.y += e0[d] * pv.y; a0.z += e0[d] * pv.z; a0.w += e0[d] * pv.w;
            a1.x += e1[d] * pv.x; a1.y += e1[d] * pv.y; a1.z += e1[d] * pv.z; a1.w += e1[d] * pv.w;
            a2.x += e2[d] * pv.x; a2.y += e2[d] * pv.y; a2.z += e2[d] * pv.z; a2.w += e2[d] * pv.w;
            a3.x += e3[d] * pv.x; a3.y += e3[d] * pv.y; a3.z += e3[d] * pv.z; a3.w += e3[d] * pv.w;
        }
        float4* nw4 = (float4*)g_nw;
        nw4[(size_t)(n0 + 0) * 1024 + o] = a0;
        nw4[(size_t)(n0 + 1) * 1024 + o] = a1;
        nw4[(size_t)(n0 + 2) * 1024 + o] = a2;
        nw4[(size_t)(n0 + 3) * 1024 + o] = a3;
    }
}

// ================= K1: tcgen05 bf16x3 GEMM (R10-proven, unchanged) =================
#define K1_SMEM (1024 + 65536)
__global__ __launch_bounds__(256) void k1_tc(const float* __restrict__ H) {
#if HAS_TCGEN05
    extern __shared__ __align__(1024) char smem[];
    const int tid = threadIdx.x, w = tid >> 5, lane = tid & 31;
    const int row0 = blockIdx.x << 7;
    uint32_t sb = su32(smem);

    if (w == 0) {
        asm volatile("tcgen05.alloc.cta_group::1.sync.aligned.shared::cta.b32 [%0], %1;"
                     :: "r"(sb), "r"(128u) : "memory");
        asm volatile("tcgen05.relinquish_alloc_permit.cta_group::1.sync.aligned;");
    }
    if (tid == 0) MBAR_INIT(sb + 16, 1);
    float* sbias = (float*)(smem + 64);
    if (tid < 128) sbias[tid] = g_bias[tid];
    __syncthreads();
    uint32_t tmem;
    asm("ld.shared.b32 %0, [%1];" : "=r"(tmem) : "r"(sb));

    char* buf = smem + 1024;
    const uint32_t bufb = sb + 1024;

    for (int c = 0; c < NCHUNK; c++) {
        if (c > 0) MBAR_WAITP(sb + 16, (uint32_t)((c - 1) & 1));

        {
            const char* bh = (const char*)g_Bhi + c * 16384 + tid * 16;
            const char* bl = (const char*)g_Blo + c * 16384 + tid * 16;
            uint32_t dh = bufb + 32768 + tid * 16;
            uint32_t dl = bufb + 49152 + tid * 16;
            #pragma unroll
            for (int i = 0; i < 4; i++) {
                cp16(dh + i * 4096, bh + i * 4096);
                cp16(dl + i * 4096, bl + i * 4096);
            }
            asm volatile("cp.async.commit_group;" ::: "memory");
        }
        #pragma unroll
        for (int it = 0; it < 4; it++) {
            int task = it * 256 + tid;
            int r = task >> 3, kq = task & 7;
            const float* hp = H + (size_t)(row0 + r) * KDIM + c * 64 + kq * 8;
            float4 u0 = *(const float4*)hp;
            float4 u1 = *(const float4*)(hp + 4);
            uint32_t hi[4], lo[4];
            bf16split(u0.x, u0.y, hi[0], lo[0]);
            bf16split(u0.z, u0.w, hi[1], lo[1]);
            bf16split(u1.x, u1.y, hi[2], lo[2]);
            bf16split(u1.z, u1.w, hi[3], lo[3]);
            int off = r * 128 + kq * 16;
            int swo = off ^ ((off >> 3) & 0x70);
            *(uint4*)(buf + swo)         = make_uint4(hi[0], hi[1], hi[2], hi[3]);
            *(uint4*)(buf + 16384 + swo) = make_uint4(lo[0], lo[1], lo[2], lo[3]);
        }
        asm volatile("cp.async.wait_group 0;" ::: "memory");
        asm volatile("fence.proxy.async.shared::cta;" ::: "memory");
        __syncthreads();

        if (w == 0 && elect1()) {
            uint64_t ah = mkdesc(bufb);
            uint64_t al = mkdesc(bufb + 16384);
            uint64_t bh = mkdesc(bufb + 32768);
            uint64_t bl = mkdesc(bufb + 49152);
            #pragma unroll
            for (int ks = 0; ks < 4; ks++) {
                uint32_t en0 = (c == 0 && ks == 0) ? 0u : 1u;
                mma_f16_ss(tmem, ah + 2 * ks, bh + 2 * ks, IDESC_BF16, en0);
                mma_f16_ss(tmem, ah + 2 * ks, bl + 2 * ks, IDESC_BF16, 1u);
                mma_f16_ss(tmem, al + 2 * ks, bh + 2 * ks, IDESC_BF16, 1u);
            }
            TC_COMMIT(sb + 16);
        }
    }

    MBAR_WAITP(sb + 16, 1u);
    asm volatile("tcgen05.fence::after_thread_sync;" ::: "memory");

    if (w < 4) {
        #pragma unroll
        for (int base = 0; base < 128; base += 32) {
            uint32_t dr[32];
            LDTM32(dr, tmem + base);
            TC_WAITLD();
            float* op = g_sim + (size_t)(row0 + w * 32 + lane) * CDIM + base;
            #pragma unroll
            for (int j = 0; j < 32; j += 4) {
                float4 o;
                o.x = __uint_as_float(dr[j + 0]) + sbias[base + j + 0];
                o.y = __uint_as_float(dr[j + 1]) + sbias[base + j + 1];
                o.z = __uint_as_float(dr[j + 2]) + sbias[base + j + 2];
                o.w = __uint_as_float(dr[j + 3]) + sbias[base + j + 3];
                *(float4*)(op + j) = o;
            }
        }
        asm volatile("tcgen05.fence::before_thread_sync;" ::: "memory");
    }
    __syncthreads();
    if (w == 0) {
        asm volatile("tcgen05.dealloc.cta_group::1.sync.aligned.b32 %0, %1;"
                     :: "r"(tmem), "r"(128u));
    }
#else
    // Generic-arch fallback (never executed on sm_103a; keeps compute_103 PTX legal).
    extern __shared__ __align__(1024) char smem[];
    float (*As)[128] = (float(*)[128])smem;
    float (*Bs)[128] = (float(*)[128])(smem + 8192);
    int tid = threadIdx.x;
    int row0 = blockIdx.x << 7;
    int ty = tid >> 4, tx = tid & 15;
    float acc[8][8] = {};
    const float* Hb = H + (size_t)row0 * KDIM;
    for (int kt = 0; kt < KDIM; kt += 16) {
        #pragma unroll
        for (int i = 0; i < 2; i++) {
            int id = tid + i * 256;
            int m = id >> 2, kk = (id & 3) << 2;
            float4 v = *(const float4*)(Hb + (size_t)m * KDIM + kt + kk);
            As[kk + 0][m] = v.x; As[kk + 1][m] = v.y;
            As[kk + 2][m] = v.z; As[kk + 3][m] = v.w;
        }
        #pragma unroll
        for (int i = 0; i < 2; i++) {
            int id = tid + i * 256;
            int k = id >> 5, n4 = (id & 31) << 2;
            *(float4*)&Bs[k][n4] = *(const float4*)(g_A + (kt + k) * CDIM + n4);
        }
        __syncthreads();
        #pragma unroll
        for (int k = 0; k < 16; k++) {
            float a[8], b[8];
            #pragma unroll
            for (int i = 0; i < 8; i++) a[i] = As[k][ty * 8 + i];
            #pragma unroll
            for (int j = 0; j < 8; j++) b[j] = Bs[k][tx * 8 + j];
            #pragma unroll
            for (int i = 0; i < 8; i++)
                #pragma unroll
                for (int j = 0; j < 8; j++) acc[i][j] += a[i] * b[j];
        }
        __syncthreads();
    }
    #pragma unroll
    for (int i = 0; i < 8; i++) {
        size_t r = row0 + ty * 8 + i;
        float* op = g_sim + r * CDIM + tx * 8;
        #pragma unroll
        for (int j = 0; j < 8; j++) op[j] = acc[i][j] + g_bias[tx * 8 + j];
    }
#endif
}

// ================= K2: register-blocked epilogue, 512 threads, 4 rows/warp =================
// Dynamic smem layout (bytes):
//   [0..16384)      snw  [64*64] float        (node weights, float2-read)
//   [16384..32768)  sLG  [64*32] float2       ({Lm,Gm})
//   [32768..65536)  satt [16 warps][128 m][4] (attn transposed; rows 16B, float4-aligned)
//   [65536..81920)  sfus [16 warps][64 f][4]  (fused transposed)
#define K2_SMEM 81920
__global__ __launch_bounds__(512) void k2_epi(float* __restrict__ out) {
    extern __shared__ __align__(16) char sm2[];
    float*  snw  = (float*)sm2;
    float2* sLG  = (float2*)(sm2 + 16384);
    int n = blockIdx.x, tid = threadIdx.x;
    int w = tid >> 5, lane = tid & 31;      // w in 0..15
    float* satt = (float*)(sm2 + 32768) + w * (128 * 4);
    float* sfus = (float*)(sm2 + 65536) + w * (64 * 4);

    {
        const float4* src = (const float4*)(g_nw + (size_t)n * 4096);
        float4* dst = (float4*)snw;
        dst[tid] = src[tid];
        dst[tid + 512] = src[tid + 512];
        for (int i = tid; i < 2048; i += 512) sLG[i] = make_float2(g_Lm[i], g_Gm[i]);
    }
    __syncthreads();

    // ---- phase 1: softmax for this warp's 4 rows (b = i*16 + w), attn -> satt[m][i] ----
    for (int i = 0; i < 4; i++) {
        int b = i * 16 + w;
        size_t row = (size_t)b * N_NODES + n;
        const float* sp = g_sim + row * CDIM;
        float v0 = sp[lane], v1 = sp[lane + 32];
        float v2 = sp[lane + 64], v3 = sp[lane + 96];

        float mx = fmaxf(v0, v1);
        #pragma unroll
        for (int o = 16; o; o >>= 1) mx = fmaxf(mx, __shfl_xor_sync(0xffffffffu, mx, o));
        float e0 = __expf(v0 - mx), e1 = __expf(v1 - mx);
        float s = e0 + e1;
        #pragma unroll
        for (int o = 16; o; o >>= 1) s += __shfl_xor_sync(0xffffffffu, s, o);
        float inv = 1.f / s;

        float mx2 = fmaxf(v2, v3);
        #pragma unroll
        for (int o = 16; o; o >>= 1) mx2 = fmaxf(mx2, __shfl_xor_sync(0xffffffffu, mx2, o));
        float e2 = __expf(v2 - mx2), e3 = __expf(v3 - mx2);
        float s2 = e2 + e3;
        #pragma unroll
        for (int o = 16; o; o >>= 1) s2 += __shfl_xor_sync(0xffffffffu, s2, o);
        float inv2 = 1.f / s2;

        satt[(lane)      * 4 + i] = e0 * inv;
        satt[(lane + 32) * 4 + i] = e1 * inv;
        satt[(lane + 64) * 4 + i] = e2 * inv2;
        satt[(lane + 96) * 4 + i] = e3 * inv2;
    }
    __syncwarp();

    // ---- phase 2: ctx, register-blocked over 4 rows; lane owns pattern p = lane ----
    float lctx[4] = {0, 0, 0, 0};
    float gctx[4] = {0, 0, 0, 0};
    #pragma unroll 8
    for (int m = 0; m < 64; m++) {
        float2 lg = sLG[m * 32 + lane];
        float4 al = *(const float4*)&satt[m * 4];
        float4 ag = *(const float4*)&satt[(m + 64) * 4];
        lctx[0] += al.x * lg.x; lctx[1] += al.y * lg.x;
        lctx[2] += al.z * lg.x; lctx[3] += al.w * lg.x;
        gctx[0] += ag.x * lg.y; gctx[1] += ag.y * lg.y;
        gctx[2] += ag.z * lg.y; gctx[3] += ag.w * lg.y;
    }
    #pragma unroll
    for (int r = 0; r < 4; r++) {
        sfus[lane * 4 + r]        = lctx[r];
        sfus[(lane + 32) * 4 + r] = gctx[r];
    }
    __syncwarp();

    // ---- phase 3: out, register-blocked; lane owns h pair (2*lane, 2*lane+1) ----
    const float2* snw2 = (const float2*)snw;
    float2 acc[4];
    #pragma unroll
    for (int r = 0; r < 4; r++) acc[r] = make_float2(0.f, 0.f);
    #pragma unroll 8
    for (int f = 0; f < 64; f++) {
        float2 wv = snw2[f * 32 + lane];
        float4 fr = *(const float4*)&sfus[f * 4];
        acc[0].x += fr.x * wv.x; acc[0].y += fr.x * wv.y;
        acc[1].x += fr.y * wv.x; acc[1].y += fr.y * wv.y;
        acc[2].x += fr.z * wv.x; acc[2].y += fr.z * wv.y;
        acc[3].x += fr.w * wv.x; acc[3].y += fr.w * wv.y;
    }
    #pragma unroll
    for (int r = 0; r < 4; r++) {
        size_t row = (size_t)(r * 16 + w) * N_NODES + n;
        *(float2*)(out + row * HID + 2 * lane) = acc[r];
    }
}

// ================= launch =================
extern "C" void kernel_launch(void* const* d_in, const int* in_sizes, int n_in,
                              void* d_out, int out_size) {
    const float* H    = (const float*)d_in[0];   // [64,1024,12,64]
    const float* G    = (const float*)d_in[1];   // [64,6,32]
    const float* L    = (const float*)d_in[2];   // [64,12,32]
    const float* Wq   = (const float*)d_in[3];   // [64,32]
    const float* bq   = (const float*)d_in[4];   // [32]
    const float* emb  = (const float*)d_in[5];   // [1024,16]
    const float* pool = (const float*)d_in[6];   // [16,64,64]
    float* out = (float*)d_out;                  // [64,1024,64]

    static bool attr_done = false;
    if (!attr_done) {
        cudaFuncSetAttribute(k1_tc, cudaFuncAttributeMaxDynamicSharedMemorySize, K1_SMEM);
        cudaFuncSetAttribute(k2_epi, cudaFuncAttributeMaxDynamicSharedMemorySize, K2_SMEM);
        attr_done = true;
    }

    // k2 stays in captured launch slot 3.
    pFold_kernel<<<13, 256>>>(G, L, Wq, bq);             // slot 0
    pNw_kernel  <<<256, 256>>>(emb, pool);               // slot 1
    k1_tc       <<<ROWS / 128, 256, K1_SMEM>>>(H);       // slot 2
    k2_epi      <<<N_NODES, 512, K2_SMEM>>>(out);        // slot 3  <-- profiled
}